// round 4
// baseline (speedup 1.0000x reference)
#include <cuda_runtime.h>
#include <cuda_bf16.h>
#include <cstdint>

// ---------------------------------------------------------------------------
// Problem constants
// ---------------------------------------------------------------------------
#define D_MODEL 1024
#define BATCH   16
#define LQ      1024
#define NBE     256
#define ML (BATCH * LQ)    // 16384
#define MB (BATCH * NBE)   // 4096

// ---------------------------------------------------------------------------
// Scratch: bf16 hi/lo planes + fp32 intermediates (__device__ globals)
// ---------------------------------------------------------------------------
__device__ __nv_bfloat16 g_qh [ML * D_MODEL], g_ql [ML * D_MODEL];   // query split
__device__ __nv_bfloat16 g_WQh[D_MODEL * D_MODEL], g_WQl[D_MODEL * D_MODEL];
__device__ __nv_bfloat16 g_WKh[D_MODEL * D_MODEL], g_WKl[D_MODEL * D_MODEL];
__device__ __nv_bfloat16 g_WOh[D_MODEL * D_MODEL], g_WOl[D_MODEL * D_MODEL];
__device__ __nv_bfloat16 g_Gh [MB * D_MODEL], g_Gl [MB * D_MODEL];   // gathered ents
__device__ __nv_bfloat16 g_Qh [ML * D_MODEL], g_Ql [ML * D_MODEL];   // Q projected
__device__ __nv_bfloat16 g_Eh [MB * D_MODEL], g_El [MB * D_MODEL];   // ENT projected
__device__ __nv_bfloat16 g_ETh[MB * D_MODEL], g_ETl[MB * D_MODEL];   // ENT^T
__device__ float         g_S  [ML * NBE];                            // scores
__device__ __nv_bfloat16 g_Wh [ML * NBE], g_Wl [ML * NBE];           // softmax weights
__device__ __nv_bfloat16 g_Vh [ML * D_MODEL], g_Vl [ML * D_MODEL];   // attn output
__device__ float         g_P  [ML * D_MODEL];                        // pre-LN

// ---------------------------------------------------------------------------
// Helpers
// ---------------------------------------------------------------------------
__device__ __forceinline__ void split1(float x, __nv_bfloat16& h, __nv_bfloat16& l) {
    h = __float2bfloat16(x);
    l = __float2bfloat16(x - __bfloat162float(h));
}

__device__ __forceinline__ void cp16(uint32_t dst, const void* src) {
    asm volatile("cp.async.cg.shared.global [%0], [%1], 16;"
                 :: "r"(dst), "l"(src) : "memory");
}

__device__ __forceinline__ void ldsm4(uint32_t* r, uint32_t addr) {
    asm volatile("ldmatrix.sync.aligned.m8n8.x4.shared.b16 {%0,%1,%2,%3}, [%4];"
                 : "=r"(r[0]), "=r"(r[1]), "=r"(r[2]), "=r"(r[3]) : "r"(addr));
}

__device__ __forceinline__ void mma_bf16(float* c, const uint32_t* a,
                                         uint32_t b0, uint32_t b1) {
    asm volatile(
        "mma.sync.aligned.m16n8k16.row.col.f32.bf16.bf16.f32 "
        "{%0,%1,%2,%3}, {%4,%5,%6,%7}, {%8,%9}, {%0,%1,%2,%3};"
        : "+f"(c[0]), "+f"(c[1]), "+f"(c[2]), "+f"(c[3])
        : "r"(a[0]), "r"(a[1]), "r"(a[2]), "r"(a[3]), "r"(b0), "r"(b1));
}

// ---------------------------------------------------------------------------
// Split-precision bf16 NT GEMM: C[bz][M,N] = A@B^T (+bias)(*rowmask)
// A,B given as hi/lo bf16 planes. 3-term: ah*bh + ah*bl + al*bh, fp32 acc.
// CTA 128x128, BK=32, 8 warps (2x4), cp.async double buffer, ldmatrix frags.
// ---------------------------------------------------------------------------
#define BKC 32
#define SKB 80                        // smem row stride bytes (40 bf16)
#define PLANE_B (128 * SKB)           // 10240 B per plane
#define STAGE_B (4 * PLANE_B)         // Ah, Al, Bh, Bl
#define GSMEM_BYTES (2 * STAGE_B)     // 81920 B

template<bool HAS_BIAS, bool MASK, bool SPLIT_OUT>
__global__ void __launch_bounds__(256, 1) gemm_sp(
    const __nv_bfloat16* __restrict__ Ahp, const __nv_bfloat16* __restrict__ Alp, long sA,
    const __nv_bfloat16* __restrict__ Bhp, const __nv_bfloat16* __restrict__ Blp, long sB,
    float* __restrict__ Cf, __nv_bfloat16* __restrict__ Ch,
    __nv_bfloat16* __restrict__ Cl, long sC,
    int N, int K,
    const float* __restrict__ bias,
    const int* __restrict__ rmask)
{
    extern __shared__ char smc[];
    const uint32_t smb = (uint32_t)__cvta_generic_to_shared(smc);

    const int tid  = threadIdx.x;
    const int wid  = tid >> 5;
    const int lane = tid & 31;
    const int wm   = wid >> 2;       // 0..1
    const int wn   = wid & 3;        // 0..3
    const int gq   = lane >> 2;
    const int tg   = lane & 3;

    const int mtile = blockIdx.y * 128;
    const int ntile = blockIdx.x * 128;
    const int bz    = blockIdx.z;
    Ahp += (long)bz * sA;  Alp += (long)bz * sA;
    Bhp += (long)bz * sB;  Blp += (long)bz * sB;

    const int nch = K >> 5;

    float acc[4][4][4];
#pragma unroll
    for (int i = 0; i < 4; i++)
#pragma unroll
        for (int j = 0; j < 4; j++)
#pragma unroll
            for (int q = 0; q < 4; q++) acc[i][j][q] = 0.f;

    // loader: per plane, 128 rows x 4 segs(16B); thread t -> row t>>1, segs (t&1)*2, +1
    const int lrow = tid >> 1;
    const int lseg = (tid & 1) * 2;
    const long aoff = (long)(mtile + lrow) * K + lseg * 8;
    const long boff = (long)(ntile + lrow) * K + lseg * 8;
    const uint32_t sdst = lrow * SKB + lseg * 16;

    auto load_chunk = [&](int c, int s) {
        const long kofs = (long)c * BKC;
        const uint32_t sb = smb + s * STAGE_B + sdst;
        cp16(sb,                          Ahp + aoff + kofs);
        cp16(sb + 16,                     Ahp + aoff + kofs + 8);
        cp16(sb + PLANE_B,                Alp + aoff + kofs);
        cp16(sb + PLANE_B + 16,           Alp + aoff + kofs + 8);
        cp16(sb + 2 * PLANE_B,            Bhp + boff + kofs);
        cp16(sb + 2 * PLANE_B + 16,       Bhp + boff + kofs + 8);
        cp16(sb + 3 * PLANE_B,            Blp + boff + kofs);
        cp16(sb + 3 * PLANE_B + 16,       Blp + boff + kofs + 8);
    };

    load_chunk(0, 0);
    asm volatile("cp.async.commit_group;" ::: "memory");

    // ldmatrix per-lane address pieces
    const int lr = (lane & 7) + ((lane >> 3) & 1) * 8;   // row 0..15 within tile
    const int lc = ((lane >> 4) & 1) * 16;               // 0 or 16 bytes (k half)

    for (int c = 0; c < nch; c++) {
        const int s = c & 1;
        if (c + 1 < nch) {
            load_chunk(c + 1, s ^ 1);
            asm volatile("cp.async.commit_group;" ::: "memory");
            asm volatile("cp.async.wait_group 1;" ::: "memory");
        } else {
            asm volatile("cp.async.wait_group 0;" ::: "memory");
        }
        __syncthreads();

        const uint32_t stb = smb + s * STAGE_B;

#pragma unroll
        for (int kk = 0; kk < 2; kk++) {
            uint32_t ah[4][4], al[4][4], bh[2][4], bl[2][4];
#pragma unroll
            for (int mt = 0; mt < 4; mt++) {
                uint32_t ad = stb + (uint32_t)(wm * 64 + mt * 16 + lr) * SKB
                            + kk * 32 + lc;
                ldsm4(ah[mt], ad);
                ldsm4(al[mt], ad + PLANE_B);
            }
#pragma unroll
            for (int h = 0; h < 2; h++) {
                uint32_t bd = stb + 2 * PLANE_B
                            + (uint32_t)(wn * 32 + h * 16 + lr) * SKB
                            + kk * 32 + lc;
                ldsm4(bh[h], bd);
                ldsm4(bl[h], bd + PLANE_B);
            }
#pragma unroll
            for (int mt = 0; mt < 4; mt++)
#pragma unroll
                for (int h = 0; h < 2; h++)
#pragma unroll
                    for (int j = 0; j < 2; j++) {
                        float* cc = acc[mt][h * 2 + j];
                        mma_bf16(cc, ah[mt], bh[h][j], bh[h][j + 2]);
                        mma_bf16(cc, ah[mt], bl[h][j], bl[h][j + 2]);
                        mma_bf16(cc, al[mt], bh[h][j], bh[h][j + 2]);
                    }
        }
        __syncthreads();
    }

    // ---- epilogue ----
#pragma unroll
    for (int mt = 0; mt < 4; mt++) {
        const int r0 = mtile + wm * 64 + mt * 16 + gq;   // rows r0, r0+8
        float rm0 = 1.f, rm1 = 1.f;
        if (MASK) {
            rm0 = (rmask[r0] < 0) ? 0.f : 1.f;
            rm1 = (rmask[r0 + 8] < 0) ? 0.f : 1.f;
        }
#pragma unroll
        for (int nt = 0; nt < 4; nt++) {
            const int col = ntile + wn * 32 + nt * 8 + tg * 2;
            float bx = 0.f, by = 0.f;
            if (HAS_BIAS) {
                float2 bb = *(const float2*)(bias + col);
                bx = bb.x; by = bb.y;
            }
            float o00 = (acc[mt][nt][0] + bx) * rm0;
            float o01 = (acc[mt][nt][1] + by) * rm0;
            float o10 = (acc[mt][nt][2] + bx) * rm1;
            float o11 = (acc[mt][nt][3] + by) * rm1;
            const long i0 = (long)bz * sC + (long)r0 * N + col;
            const long i1 = i0 + (long)8 * N;
            if (SPLIT_OUT) {
                __nv_bfloat162 h2, l2;
                split1(o00, h2.x, l2.x); split1(o01, h2.y, l2.y);
                *(__nv_bfloat162*)(Ch + i0) = h2;
                *(__nv_bfloat162*)(Cl + i0) = l2;
                split1(o10, h2.x, l2.x); split1(o11, h2.y, l2.y);
                *(__nv_bfloat162*)(Ch + i1) = h2;
                *(__nv_bfloat162*)(Cl + i1) = l2;
            } else {
                *(float2*)(Cf + i0) = make_float2(o00, o01);
                *(float2*)(Cf + i1) = make_float2(o10, o11);
            }
        }
    }
}

// ---------------------------------------------------------------------------
// Elementwise fp32 -> (hi, lo) bf16 split. n multiple of 1024.
// ---------------------------------------------------------------------------
__global__ void split_f32(const float* __restrict__ x,
                          __nv_bfloat16* __restrict__ h,
                          __nv_bfloat16* __restrict__ l, int n4)
{
    int i = blockIdx.x * blockDim.x + threadIdx.x;
    if (i >= n4) return;
    float4 v = ((const float4*)x)[i];
    __nv_bfloat16 hh[4], ll[4];
    split1(v.x, hh[0], ll[0]); split1(v.y, hh[1], ll[1]);
    split1(v.z, hh[2], ll[2]); split1(v.w, hh[3], ll[3]);
    ((uint2*)h)[i] = *(uint2*)hh;
    ((uint2*)l)[i] = *(uint2*)ll;
}

// ---------------------------------------------------------------------------
// Gather + split: G[r,:] = split(ent_emb[max(idx[r],0), :])
// ---------------------------------------------------------------------------
__global__ void gather_split(const float* __restrict__ E,
                             const int* __restrict__ idx,
                             __nv_bfloat16* __restrict__ Gh,
                             __nv_bfloat16* __restrict__ Gl)
{
    const int r = blockIdx.x;
    int s = idx[r];
    if (s < 0) s = 0;
    const float4* src = (const float4*)(E + (long)s * D_MODEL);
    const int i = threadIdx.x;                 // 256 threads x 4 floats
    float4 v = src[i];
    __nv_bfloat16 hh[4], ll[4];
    split1(v.x, hh[0], ll[0]); split1(v.y, hh[1], ll[1]);
    split1(v.z, hh[2], ll[2]); split1(v.w, hh[3], ll[3]);
    ((uint2*)(Gh + (long)r * D_MODEL))[i] = *(uint2*)hh;
    ((uint2*)(Gl + (long)r * D_MODEL))[i] = *(uint2*)ll;
}

// ---------------------------------------------------------------------------
// Per-batch bf16 transpose of both planes: z = batch*2 + plane
// ---------------------------------------------------------------------------
__global__ void transpose_bf16(const __nv_bfloat16* __restrict__ ih,
                               const __nv_bfloat16* __restrict__ il,
                               __nv_bfloat16* __restrict__ oh,
                               __nv_bfloat16* __restrict__ ol)
{
    __shared__ __nv_bfloat16 t[32][34];
    const int b = blockIdx.z >> 1;
    const bool lo = blockIdx.z & 1;
    const __nv_bfloat16* I = (lo ? il : ih) + (long)b * NBE * D_MODEL;
    __nv_bfloat16*       O = (lo ? ol : oh) + (long)b * NBE * D_MODEL;
    const int c0 = blockIdx.x * 32;     // D cols
    const int r0 = blockIdx.y * 32;     // NBE rows
    const int tx = threadIdx.x, ty = threadIdx.y;
#pragma unroll
    for (int i = 0; i < 32; i += 8)
        t[ty + i][tx] = I[(long)(r0 + ty + i) * D_MODEL + c0 + tx];
    __syncthreads();
#pragma unroll
    for (int i = 0; i < 32; i += 8)
        O[(long)(c0 + ty + i) * NBE + r0 + tx] = t[tx][ty + i];
}

// ---------------------------------------------------------------------------
// Masked softmax over NB=256 + d^-0.5 scale, output split to bf16 planes.
// ---------------------------------------------------------------------------
__global__ void softmax_split(const float* __restrict__ S,
                              const int* __restrict__ idx,
                              __nv_bfloat16* __restrict__ Wh,
                              __nv_bfloat16* __restrict__ Wl)
{
    const int row = blockIdx.x;
    const int b   = row >> 10;
    const int n   = threadIdx.x;
    const long off = (long)row * NBE + n;

    float s = S[off];
    if (idx[b * NBE + n] < 0) s = -100000.0f;

    __shared__ float red[8];
    float m = s;
#pragma unroll
    for (int o = 16; o; o >>= 1) m = fmaxf(m, __shfl_xor_sync(0xffffffffu, m, o));
    if ((n & 31) == 0) red[n >> 5] = m;
    __syncthreads();
    float mall = red[0];
#pragma unroll
    for (int i = 1; i < 8; i++) mall = fmaxf(mall, red[i]);

    float e = expf(s - mall);
    __syncthreads();
    float t = e;
#pragma unroll
    for (int o = 16; o; o >>= 1) t += __shfl_xor_sync(0xffffffffu, t, o);
    if ((n & 31) == 0) red[n >> 5] = t;
    __syncthreads();
    float sum = 0.f;
#pragma unroll
    for (int i = 0; i < 8; i++) sum += red[i];

    float w = e * (0.03125f / sum);
    __nv_bfloat16 h, l;
    split1(w, h, l);
    Wh[off] = h;
    Wl[off] = l;
}

// ---------------------------------------------------------------------------
// Row LayerNorm over D=1024 (biased var, eps=1e-5).
// ---------------------------------------------------------------------------
__global__ void layernorm_k(const float* __restrict__ X,
                            const float* __restrict__ g,
                            const float* __restrict__ b,
                            float* __restrict__ O)
{
    const int row = blockIdx.x;
    const int t   = threadIdx.x;
    const float* x = X + (long)row * D_MODEL;

    float4 v = *(const float4*)(x + t * 4);
    float s  = v.x + v.y + v.z + v.w;
    float sq = v.x * v.x + v.y * v.y + v.z * v.z + v.w * v.w;

    __shared__ float rs[8], rq[8];
#pragma unroll
    for (int o = 16; o; o >>= 1) {
        s  += __shfl_xor_sync(0xffffffffu, s,  o);
        sq += __shfl_xor_sync(0xffffffffu, sq, o);
    }
    if ((t & 31) == 0) { rs[t >> 5] = s; rq[t >> 5] = sq; }
    __syncthreads();
    float S = 0.f, Q = 0.f;
#pragma unroll
    for (int i = 0; i < 8; i++) { S += rs[i]; Q += rq[i]; }

    float mu  = S * (1.f / 1024.f);
    float var = Q * (1.f / 1024.f) - mu * mu;
    float inv = rsqrtf(var + 1e-5f);

    float4 gg = *(const float4*)(g + t * 4);
    float4 bb = *(const float4*)(b + t * 4);
    float4 o;
    o.x = (v.x - mu) * inv * gg.x + bb.x;
    o.y = (v.y - mu) * inv * gg.y + bb.y;
    o.z = (v.z - mu) * inv * gg.z + bb.z;
    o.w = (v.w - mu) * inv * gg.w + bb.w;
    *(float4*)(O + (long)row * D_MODEL + t * 4) = o;
}

// ---------------------------------------------------------------------------
extern "C" void kernel_launch(void* const* d_in, const int* in_sizes, int n_in,
                              void* d_out, int out_size)
{
    const float* query   = (const float*)d_in[0];
    const float* ent_emb = (const float*)d_in[1];
    const int*   idx     = (const int*)  d_in[2];
    const float* WQ_w = (const float*)d_in[4];
    const float* WQ_b = (const float*)d_in[5];
    const float* WK_w = (const float*)d_in[6];
    const float* WK_b = (const float*)d_in[7];
    const float* WO_w = (const float*)d_in[8];
    const float* WO_b = (const float*)d_in[9];
    const float* ln_g = (const float*)d_in[10];
    const float* ln_b = (const float*)d_in[11];
    float* out = (float*)d_out;

    __nv_bfloat16 *qh, *ql, *WQh, *WQl, *WKh, *WKl, *WOh, *WOl;
    __nv_bfloat16 *Gh, *Gl, *Qh, *Ql, *Eh, *El, *ETh, *ETl, *Wh, *Wl, *Vh, *Vl;
    float *S, *P;
    cudaGetSymbolAddress((void**)&qh,  g_qh);  cudaGetSymbolAddress((void**)&ql,  g_ql);
    cudaGetSymbolAddress((void**)&WQh, g_WQh); cudaGetSymbolAddress((void**)&WQl, g_WQl);
    cudaGetSymbolAddress((void**)&WKh, g_WKh); cudaGetSymbolAddress((void**)&WKl, g_WKl);
    cudaGetSymbolAddress((void**)&WOh, g_WOh); cudaGetSymbolAddress((void**)&WOl, g_WOl);
    cudaGetSymbolAddress((void**)&Gh,  g_Gh);  cudaGetSymbolAddress((void**)&Gl,  g_Gl);
    cudaGetSymbolAddress((void**)&Qh,  g_Qh);  cudaGetSymbolAddress((void**)&Ql,  g_Ql);
    cudaGetSymbolAddress((void**)&Eh,  g_Eh);  cudaGetSymbolAddress((void**)&El,  g_El);
    cudaGetSymbolAddress((void**)&ETh, g_ETh); cudaGetSymbolAddress((void**)&ETl, g_ETl);
    cudaGetSymbolAddress((void**)&Wh,  g_Wh);  cudaGetSymbolAddress((void**)&Wl,  g_Wl);
    cudaGetSymbolAddress((void**)&Vh,  g_Vh);  cudaGetSymbolAddress((void**)&Vl,  g_Vl);
    cudaGetSymbolAddress((void**)&S,   g_S);
    cudaGetSymbolAddress((void**)&P,   g_P);

    cudaFuncSetAttribute((const void*)gemm_sp<true,  false, true >,
        cudaFuncAttributeMaxDynamicSharedMemorySize, GSMEM_BYTES);
    cudaFuncSetAttribute((const void*)gemm_sp<true,  true,  true >,
        cudaFuncAttributeMaxDynamicSharedMemorySize, GSMEM_BYTES);
    cudaFuncSetAttribute((const void*)gemm_sp<false, false, false>,
        cudaFuncAttributeMaxDynamicSharedMemorySize, GSMEM_BYTES);
    cudaFuncSetAttribute((const void*)gemm_sp<false, false, true >,
        cudaFuncAttributeMaxDynamicSharedMemorySize, GSMEM_BYTES);
    cudaFuncSetAttribute((const void*)gemm_sp<true,  false, false>,
        cudaFuncAttributeMaxDynamicSharedMemorySize, GSMEM_BYTES);

    // 0. split raw inputs
    split_f32<<<(ML * D_MODEL / 4 + 255) / 256, 256>>>(query, qh, ql, ML * D_MODEL / 4);
    split_f32<<<(D_MODEL * D_MODEL / 4 + 255) / 256, 256>>>(WQ_w, WQh, WQl, D_MODEL * D_MODEL / 4);
    split_f32<<<(D_MODEL * D_MODEL / 4 + 255) / 256, 256>>>(WK_w, WKh, WKl, D_MODEL * D_MODEL / 4);
    split_f32<<<(D_MODEL * D_MODEL / 4 + 255) / 256, 256>>>(WO_w, WOh, WOl, D_MODEL * D_MODEL / 4);

    // 1. gather + split entity rows
    gather_split<<<MB, 256>>>(ent_emb, idx, Gh, Gl);

    // 2. Q = query @ WQ^T + bQ  -> split planes
    gemm_sp<true, false, true><<<dim3(8, 128, 1), 256, GSMEM_BYTES>>>(
        qh, ql, 0, WQh, WQl, 0, nullptr, Qh, Ql, 0, D_MODEL, D_MODEL, WQ_b, nullptr);

    // 3. ENT = (G @ WK^T + bK) * mask -> split planes
    gemm_sp<true, true, true><<<dim3(8, 32, 1), 256, GSMEM_BYTES>>>(
        Gh, Gl, 0, WKh, WKl, 0, nullptr, Eh, El, 0, D_MODEL, D_MODEL, WK_b, idx);

    // 4. transpose ENT planes
    transpose_bf16<<<dim3(32, 8, BATCH * 2), dim3(32, 8)>>>(Eh, El, ETh, ETl);

    // 5. S[b] = Q[b] @ ENT[b]^T  -> fp32
    gemm_sp<false, false, false><<<dim3(2, 8, BATCH), 256, GSMEM_BYTES>>>(
        Qh, Ql, (long)LQ * D_MODEL, Eh, El, (long)NBE * D_MODEL,
        S, nullptr, nullptr, (long)LQ * NBE, NBE, D_MODEL, nullptr, nullptr);

    // 6. masked softmax + scale -> split planes
    softmax_split<<<ML, NBE>>>(S, idx, Wh, Wl);

    // 7. V[b] = W[b] @ ENTT[b]^T (= W @ ENT) -> split planes
    gemm_sp<false, false, true><<<dim3(8, 8, BATCH), 256, GSMEM_BYTES>>>(
        Wh, Wl, (long)LQ * NBE, ETh, ETl, (long)D_MODEL * NBE,
        nullptr, Vh, Vl, (long)LQ * D_MODEL, D_MODEL, NBE, nullptr, nullptr);

    // 8. P = V @ WO^T + bO -> fp32
    gemm_sp<true, false, false><<<dim3(8, 128, 1), 256, GSMEM_BYTES>>>(
        Vh, Vl, 0, WOh, WOl, 0, P, nullptr, nullptr, 0, D_MODEL, D_MODEL, WO_b, nullptr);

    // 9. LayerNorm -> out
    layernorm_k<<<ML, 256>>>(P, ln_g, ln_b, out);
}

// round 5
// speedup vs baseline: 1.0292x; 1.0292x over previous
#include <cuda_runtime.h>
#include <cuda_bf16.h>
#include <cstdint>

// ---------------------------------------------------------------------------
// Problem constants
// ---------------------------------------------------------------------------
#define D_MODEL 1024
#define BATCH   16
#define LQ      1024
#define NBE     256
#define ML (BATCH * LQ)    // 16384
#define MB (BATCH * NBE)   // 4096

// ---------------------------------------------------------------------------
// Scratch: bf16 hi/lo planes + fp32 intermediates (__device__ globals)
// ---------------------------------------------------------------------------
__device__ __nv_bfloat16 g_qh [ML * D_MODEL], g_ql [ML * D_MODEL];
__device__ __nv_bfloat16 g_WQh[D_MODEL * D_MODEL], g_WQl[D_MODEL * D_MODEL];
__device__ __nv_bfloat16 g_WKh[D_MODEL * D_MODEL], g_WKl[D_MODEL * D_MODEL];
__device__ __nv_bfloat16 g_WOh[D_MODEL * D_MODEL], g_WOl[D_MODEL * D_MODEL];
__device__ __nv_bfloat16 g_Gh [MB * D_MODEL], g_Gl [MB * D_MODEL];
__device__ __nv_bfloat16 g_Qh [ML * D_MODEL], g_Ql [ML * D_MODEL];
__device__ __nv_bfloat16 g_Eh [MB * D_MODEL], g_El [MB * D_MODEL];
__device__ __nv_bfloat16 g_ETh[MB * D_MODEL], g_ETl[MB * D_MODEL];
__device__ float         g_S  [ML * NBE];
__device__ __nv_bfloat16 g_Wh [ML * NBE], g_Wl [ML * NBE];
__device__ __nv_bfloat16 g_Vh [ML * D_MODEL], g_Vl [ML * D_MODEL];
__device__ float         g_P  [ML * D_MODEL];

// ---------------------------------------------------------------------------
// Helpers
// ---------------------------------------------------------------------------
__device__ __forceinline__ void split1(float x, __nv_bfloat16& h, __nv_bfloat16& l) {
    h = __float2bfloat16(x);
    l = __float2bfloat16(x - __bfloat162float(h));
}

__device__ __forceinline__ void cp16(uint32_t dst, const void* src) {
    asm volatile("cp.async.cg.shared.global [%0], [%1], 16;"
                 :: "r"(dst), "l"(src) : "memory");
}

__device__ __forceinline__ void ldsm4(uint32_t* r, uint32_t addr) {
    asm volatile("ldmatrix.sync.aligned.m8n8.x4.shared.b16 {%0,%1,%2,%3}, [%4];"
                 : "=r"(r[0]), "=r"(r[1]), "=r"(r[2]), "=r"(r[3]) : "r"(addr));
}

__device__ __forceinline__ void mma_bf16(float* c, const uint32_t* a,
                                         uint32_t b0, uint32_t b1) {
    asm volatile(
        "mma.sync.aligned.m16n8k16.row.col.f32.bf16.bf16.f32 "
        "{%0,%1,%2,%3}, {%4,%5,%6,%7}, {%8,%9}, {%0,%1,%2,%3};"
        : "+f"(c[0]), "+f"(c[1]), "+f"(c[2]), "+f"(c[3])
        : "r"(a[0]), "r"(a[1]), "r"(a[2]), "r"(a[3]), "r"(b0), "r"(b1));
}

// ---------------------------------------------------------------------------
// Split-precision bf16 NT GEMM: C[bz][M,N] = A@B^T (+bias)(*rowmask)
// 3-term: ah*bh + ah*bl + al*bh, fp32 accumulate.
// CTA 128x128, BK=32, 16 warps (4x4, warp tile 32x32),
// 3-stage cp.async pipeline, ldmatrix fragments.
// ---------------------------------------------------------------------------
#define BKC 32
#define SKB 80                        // smem row stride bytes (40 bf16)
#define PLANE_B (128 * SKB)           // 10240 B
#define STAGE_B (4 * PLANE_B)         // Ah, Al, Bh, Bl = 40960 B
#define NSTAGE 3
#define GSMEM_BYTES (NSTAGE * STAGE_B)   // 122880 B

template<bool HAS_BIAS, bool MASK, bool SPLIT_OUT>
__global__ void __launch_bounds__(512, 1) gemm_sp(
    const __nv_bfloat16* __restrict__ Ahp, const __nv_bfloat16* __restrict__ Alp, long sA,
    const __nv_bfloat16* __restrict__ Bhp, const __nv_bfloat16* __restrict__ Blp, long sB,
    float* __restrict__ Cf, __nv_bfloat16* __restrict__ Ch,
    __nv_bfloat16* __restrict__ Cl, long sC,
    int N, int K,
    const float* __restrict__ bias,
    const int* __restrict__ rmask)
{
    extern __shared__ char smc[];
    const uint32_t smb = (uint32_t)__cvta_generic_to_shared(smc);

    const int tid  = threadIdx.x;
    const int wid  = tid >> 5;
    const int lane = tid & 31;
    const int wm   = wid >> 2;       // 0..3 (32-row slab)
    const int wn   = wid & 3;        // 0..3 (32-col slab)
    const int gq   = lane >> 2;
    const int tg   = lane & 3;

    const int mtile = blockIdx.y * 128;
    const int ntile = blockIdx.x * 128;
    const int bz    = blockIdx.z;
    Ahp += (long)bz * sA;  Alp += (long)bz * sA;
    Bhp += (long)bz * sB;  Blp += (long)bz * sB;

    const int nch = K >> 5;

    float acc[2][4][4];
#pragma unroll
    for (int i = 0; i < 2; i++)
#pragma unroll
        for (int j = 0; j < 4; j++)
#pragma unroll
            for (int q = 0; q < 4; q++) acc[i][j][q] = 0.f;

    // loader: 512 threads; per plane 128 rows x 4 segs(16B) = 512 slots.
    const int lrow = tid >> 2;
    const int lseg = tid & 3;
    const long aoff = (long)(mtile + lrow) * K + lseg * 8;
    const long boff = (long)(ntile + lrow) * K + lseg * 8;
    const uint32_t sdst = lrow * SKB + lseg * 16;

    auto load_chunk = [&](int c, int s) {
        const long kofs = (long)c * BKC;
        const uint32_t sb = smb + s * STAGE_B + sdst;
        cp16(sb,               Ahp + aoff + kofs);
        cp16(sb + PLANE_B,     Alp + aoff + kofs);
        cp16(sb + 2 * PLANE_B, Bhp + boff + kofs);
        cp16(sb + 3 * PLANE_B, Blp + boff + kofs);
    };

    load_chunk(0, 0);
    asm volatile("cp.async.commit_group;" ::: "memory");
    if (nch > 1) load_chunk(1, 1);
    asm volatile("cp.async.commit_group;" ::: "memory");

    // ldmatrix per-lane address pieces
    const int lr = (lane & 7) + ((lane >> 3) & 1) * 8;   // row 0..15 within tile
    const int lc = ((lane >> 4) & 1) * 16;               // 0/16 bytes (k half)

    int stage = 0;
    for (int c = 0; c < nch; c++) {
        asm volatile("cp.async.wait_group 1;" ::: "memory");
        __syncthreads();

        const int cn = c + 2;
        if (cn < nch) {
            int sn = stage + 2; if (sn >= NSTAGE) sn -= NSTAGE;
            load_chunk(cn, sn);
        }
        asm volatile("cp.async.commit_group;" ::: "memory");

        const uint32_t stb = smb + stage * STAGE_B;

#pragma unroll
        for (int kk = 0; kk < 2; kk++) {
            uint32_t ah[2][4], al[2][4], bh[2][4], bl[2][4];
#pragma unroll
            for (int mt = 0; mt < 2; mt++) {
                uint32_t ad = stb + (uint32_t)(wm * 32 + mt * 16 + lr) * SKB
                            + kk * 32 + lc;
                ldsm4(ah[mt], ad);
                ldsm4(al[mt], ad + PLANE_B);
            }
#pragma unroll
            for (int h = 0; h < 2; h++) {
                uint32_t bd = stb + 2 * PLANE_B
                            + (uint32_t)(wn * 32 + h * 16 + lr) * SKB
                            + kk * 32 + lc;
                ldsm4(bh[h], bd);
                ldsm4(bl[h], bd + PLANE_B);
            }
#pragma unroll
            for (int mt = 0; mt < 2; mt++)
#pragma unroll
                for (int h = 0; h < 2; h++)
#pragma unroll
                    for (int j = 0; j < 2; j++) {
                        float* cc = acc[mt][h * 2 + j];
                        mma_bf16(cc, ah[mt], bh[h][j], bh[h][j + 2]);
                        mma_bf16(cc, ah[mt], bl[h][j], bl[h][j + 2]);
                        mma_bf16(cc, al[mt], bh[h][j], bh[h][j + 2]);
                    }
        }
        __syncthreads();
        stage++; if (stage >= NSTAGE) stage = 0;
    }

    // ---- epilogue ----
#pragma unroll
    for (int mt = 0; mt < 2; mt++) {
        const int r0 = mtile + wm * 32 + mt * 16 + gq;   // rows r0, r0+8
        float rm0 = 1.f, rm1 = 1.f;
        if (MASK) {
            rm0 = (rmask[r0] < 0) ? 0.f : 1.f;
            rm1 = (rmask[r0 + 8] < 0) ? 0.f : 1.f;
        }
#pragma unroll
        for (int nt = 0; nt < 4; nt++) {
            const int col = ntile + wn * 32 + nt * 8 + tg * 2;
            float bx = 0.f, by = 0.f;
            if (HAS_BIAS) {
                float2 bb = *(const float2*)(bias + col);
                bx = bb.x; by = bb.y;
            }
            float o00 = (acc[mt][nt][0] + bx) * rm0;
            float o01 = (acc[mt][nt][1] + by) * rm0;
            float o10 = (acc[mt][nt][2] + bx) * rm1;
            float o11 = (acc[mt][nt][3] + by) * rm1;
            const long i0 = (long)bz * sC + (long)r0 * N + col;
            const long i1 = i0 + (long)8 * N;
            if (SPLIT_OUT) {
                __nv_bfloat162 h2, l2;
                split1(o00, h2.x, l2.x); split1(o01, h2.y, l2.y);
                *(__nv_bfloat162*)(Ch + i0) = h2;
                *(__nv_bfloat162*)(Cl + i0) = l2;
                split1(o10, h2.x, l2.x); split1(o11, h2.y, l2.y);
                *(__nv_bfloat162*)(Ch + i1) = h2;
                *(__nv_bfloat162*)(Cl + i1) = l2;
            } else {
                *(float2*)(Cf + i0) = make_float2(o00, o01);
                *(float2*)(Cf + i1) = make_float2(o10, o11);
            }
        }
    }
}

// ---------------------------------------------------------------------------
// Elementwise fp32 -> (hi, lo) bf16 split.
// ---------------------------------------------------------------------------
__global__ void split_f32(const float* __restrict__ x,
                          __nv_bfloat16* __restrict__ h,
                          __nv_bfloat16* __restrict__ l, int n4)
{
    int i = blockIdx.x * blockDim.x + threadIdx.x;
    if (i >= n4) return;
    float4 v = ((const float4*)x)[i];
    __nv_bfloat16 hh[4], ll[4];
    split1(v.x, hh[0], ll[0]); split1(v.y, hh[1], ll[1]);
    split1(v.z, hh[2], ll[2]); split1(v.w, hh[3], ll[3]);
    ((uint2*)h)[i] = *(uint2*)hh;
    ((uint2*)l)[i] = *(uint2*)ll;
}

// ---------------------------------------------------------------------------
// Gather + split: G[r,:] = split(ent_emb[max(idx[r],0), :])
// ---------------------------------------------------------------------------
__global__ void gather_split(const float* __restrict__ E,
                             const int* __restrict__ idx,
                             __nv_bfloat16* __restrict__ Gh,
                             __nv_bfloat16* __restrict__ Gl)
{
    const int r = blockIdx.x;
    int s = idx[r];
    if (s < 0) s = 0;
    const float4* src = (const float4*)(E + (long)s * D_MODEL);
    const int i = threadIdx.x;
    float4 v = src[i];
    __nv_bfloat16 hh[4], ll[4];
    split1(v.x, hh[0], ll[0]); split1(v.y, hh[1], ll[1]);
    split1(v.z, hh[2], ll[2]); split1(v.w, hh[3], ll[3]);
    ((uint2*)(Gh + (long)r * D_MODEL))[i] = *(uint2*)hh;
    ((uint2*)(Gl + (long)r * D_MODEL))[i] = *(uint2*)ll;
}

// ---------------------------------------------------------------------------
// Per-batch bf16 transpose of both planes: z = batch*2 + plane
// ---------------------------------------------------------------------------
__global__ void transpose_bf16(const __nv_bfloat16* __restrict__ ih,
                               const __nv_bfloat16* __restrict__ il,
                               __nv_bfloat16* __restrict__ oh,
                               __nv_bfloat16* __restrict__ ol)
{
    __shared__ __nv_bfloat16 t[32][34];
    const int b = blockIdx.z >> 1;
    const bool lo = blockIdx.z & 1;
    const __nv_bfloat16* I = (lo ? il : ih) + (long)b * NBE * D_MODEL;
    __nv_bfloat16*       O = (lo ? ol : oh) + (long)b * NBE * D_MODEL;
    const int c0 = blockIdx.x * 32;
    const int r0 = blockIdx.y * 32;
    const int tx = threadIdx.x, ty = threadIdx.y;
#pragma unroll
    for (int i = 0; i < 32; i += 8)
        t[ty + i][tx] = I[(long)(r0 + ty + i) * D_MODEL + c0 + tx];
    __syncthreads();
#pragma unroll
    for (int i = 0; i < 32; i += 8)
        O[(long)(c0 + ty + i) * NBE + r0 + tx] = t[tx][ty + i];
}

// ---------------------------------------------------------------------------
// Masked softmax over NB=256 + d^-0.5 scale, output split to bf16 planes.
// ---------------------------------------------------------------------------
__global__ void softmax_split(const float* __restrict__ S,
                              const int* __restrict__ idx,
                              __nv_bfloat16* __restrict__ Wh,
                              __nv_bfloat16* __restrict__ Wl)
{
    const int row = blockIdx.x;
    const int b   = row >> 10;
    const int n   = threadIdx.x;
    const long off = (long)row * NBE + n;

    float s = S[off];
    if (idx[b * NBE + n] < 0) s = -100000.0f;

    __shared__ float red[8];
    float m = s;
#pragma unroll
    for (int o = 16; o; o >>= 1) m = fmaxf(m, __shfl_xor_sync(0xffffffffu, m, o));
    if ((n & 31) == 0) red[n >> 5] = m;
    __syncthreads();
    float mall = red[0];
#pragma unroll
    for (int i = 1; i < 8; i++) mall = fmaxf(mall, red[i]);

    float e = expf(s - mall);
    __syncthreads();
    float t = e;
#pragma unroll
    for (int o = 16; o; o >>= 1) t += __shfl_xor_sync(0xffffffffu, t, o);
    if ((n & 31) == 0) red[n >> 5] = t;
    __syncthreads();
    float sum = 0.f;
#pragma unroll
    for (int i = 0; i < 8; i++) sum += red[i];

    float w = e * (0.03125f / sum);
    __nv_bfloat16 h, l;
    split1(w, h, l);
    Wh[off] = h;
    Wl[off] = l;
}

// ---------------------------------------------------------------------------
// Row LayerNorm over D=1024 (biased var, eps=1e-5).
// ---------------------------------------------------------------------------
__global__ void layernorm_k(const float* __restrict__ X,
                            const float* __restrict__ g,
                            const float* __restrict__ b,
                            float* __restrict__ O)
{
    const int row = blockIdx.x;
    const int t   = threadIdx.x;
    const float* x = X + (long)row * D_MODEL;

    float4 v = *(const float4*)(x + t * 4);
    float s  = v.x + v.y + v.z + v.w;
    float sq = v.x * v.x + v.y * v.y + v.z * v.z + v.w * v.w;

    __shared__ float rs[8], rq[8];
#pragma unroll
    for (int o = 16; o; o >>= 1) {
        s  += __shfl_xor_sync(0xffffffffu, s,  o);
        sq += __shfl_xor_sync(0xffffffffu, sq, o);
    }
    if ((t & 31) == 0) { rs[t >> 5] = s; rq[t >> 5] = sq; }
    __syncthreads();
    float S = 0.f, Q = 0.f;
#pragma unroll
    for (int i = 0; i < 8; i++) { S += rs[i]; Q += rq[i]; }

    float mu  = S * (1.f / 1024.f);
    float var = Q * (1.f / 1024.f) - mu * mu;
    float inv = rsqrtf(var + 1e-5f);

    float4 gg = *(const float4*)(g + t * 4);
    float4 bb = *(const float4*)(b + t * 4);
    float4 o;
    o.x = (v.x - mu) * inv * gg.x + bb.x;
    o.y = (v.y - mu) * inv * gg.y + bb.y;
    o.z = (v.z - mu) * inv * gg.z + bb.z;
    o.w = (v.w - mu) * inv * gg.w + bb.w;
    *(float4*)(O + (long)row * D_MODEL + t * 4) = o;
}

// ---------------------------------------------------------------------------
extern "C" void kernel_launch(void* const* d_in, const int* in_sizes, int n_in,
                              void* d_out, int out_size)
{
    const float* query   = (const float*)d_in[0];
    const float* ent_emb = (const float*)d_in[1];
    const int*   idx     = (const int*)  d_in[2];
    const float* WQ_w = (const float*)d_in[4];
    const float* WQ_b = (const float*)d_in[5];
    const float* WK_w = (const float*)d_in[6];
    const float* WK_b = (const float*)d_in[7];
    const float* WO_w = (const float*)d_in[8];
    const float* WO_b = (const float*)d_in[9];
    const float* ln_g = (const float*)d_in[10];
    const float* ln_b = (const float*)d_in[11];
    float* out = (float*)d_out;

    __nv_bfloat16 *qh, *ql, *WQh, *WQl, *WKh, *WKl, *WOh, *WOl;
    __nv_bfloat16 *Gh, *Gl, *Qh, *Ql, *Eh, *El, *ETh, *ETl, *Wh, *Wl, *Vh, *Vl;
    float *S, *P;
    cudaGetSymbolAddress((void**)&qh,  g_qh);  cudaGetSymbolAddress((void**)&ql,  g_ql);
    cudaGetSymbolAddress((void**)&WQh, g_WQh); cudaGetSymbolAddress((void**)&WQl, g_WQl);
    cudaGetSymbolAddress((void**)&WKh, g_WKh); cudaGetSymbolAddress((void**)&WKl, g_WKl);
    cudaGetSymbolAddress((void**)&WOh, g_WOh); cudaGetSymbolAddress((void**)&WOl, g_WOl);
    cudaGetSymbolAddress((void**)&Gh,  g_Gh);  cudaGetSymbolAddress((void**)&Gl,  g_Gl);
    cudaGetSymbolAddress((void**)&Qh,  g_Qh);  cudaGetSymbolAddress((void**)&Ql,  g_Ql);
    cudaGetSymbolAddress((void**)&Eh,  g_Eh);  cudaGetSymbolAddress((void**)&El,  g_El);
    cudaGetSymbolAddress((void**)&ETh, g_ETh); cudaGetSymbolAddress((void**)&ETl, g_ETl);
    cudaGetSymbolAddress((void**)&Wh,  g_Wh);  cudaGetSymbolAddress((void**)&Wl,  g_Wl);
    cudaGetSymbolAddress((void**)&Vh,  g_Vh);  cudaGetSymbolAddress((void**)&Vl,  g_Vl);
    cudaGetSymbolAddress((void**)&S,   g_S);
    cudaGetSymbolAddress((void**)&P,   g_P);

    cudaFuncSetAttribute((const void*)gemm_sp<true,  false, true >,
        cudaFuncAttributeMaxDynamicSharedMemorySize, GSMEM_BYTES);
    cudaFuncSetAttribute((const void*)gemm_sp<true,  true,  true >,
        cudaFuncAttributeMaxDynamicSharedMemorySize, GSMEM_BYTES);
    cudaFuncSetAttribute((const void*)gemm_sp<false, false, false>,
        cudaFuncAttributeMaxDynamicSharedMemorySize, GSMEM_BYTES);
    cudaFuncSetAttribute((const void*)gemm_sp<false, false, true >,
        cudaFuncAttributeMaxDynamicSharedMemorySize, GSMEM_BYTES);
    cudaFuncSetAttribute((const void*)gemm_sp<true,  false, false>,
        cudaFuncAttributeMaxDynamicSharedMemorySize, GSMEM_BYTES);

    // 0. split raw inputs
    split_f32<<<(ML * D_MODEL / 4 + 255) / 256, 256>>>(query, qh, ql, ML * D_MODEL / 4);
    split_f32<<<(D_MODEL * D_MODEL / 4 + 255) / 256, 256>>>(WQ_w, WQh, WQl, D_MODEL * D_MODEL / 4);
    split_f32<<<(D_MODEL * D_MODEL / 4 + 255) / 256, 256>>>(WK_w, WKh, WKl, D_MODEL * D_MODEL / 4);
    split_f32<<<(D_MODEL * D_MODEL / 4 + 255) / 256, 256>>>(WO_w, WOh, WOl, D_MODEL * D_MODEL / 4);

    // 1. gather + split entity rows
    gather_split<<<MB, 256>>>(ent_emb, idx, Gh, Gl);

    // 2. Q = query @ WQ^T + bQ  -> split planes
    gemm_sp<true, false, true><<<dim3(8, 128, 1), 512, GSMEM_BYTES>>>(
        qh, ql, 0, WQh, WQl, 0, nullptr, Qh, Ql, 0, D_MODEL, D_MODEL, WQ_b, nullptr);

    // 3. ENT = (G @ WK^T + bK) * mask -> split planes
    gemm_sp<true, true, true><<<dim3(8, 32, 1), 512, GSMEM_BYTES>>>(
        Gh, Gl, 0, WKh, WKl, 0, nullptr, Eh, El, 0, D_MODEL, D_MODEL, WK_b, idx);

    // 4. transpose ENT planes
    transpose_bf16<<<dim3(32, 8, BATCH * 2), dim3(32, 8)>>>(Eh, El, ETh, ETl);

    // 5. S[b] = Q[b] @ ENT[b]^T  -> fp32
    gemm_sp<false, false, false><<<dim3(2, 8, BATCH), 512, GSMEM_BYTES>>>(
        Qh, Ql, (long)LQ * D_MODEL, Eh, El, (long)NBE * D_MODEL,
        S, nullptr, nullptr, (long)LQ * NBE, NBE, D_MODEL, nullptr, nullptr);

    // 6. masked softmax + scale -> split planes
    softmax_split<<<ML, NBE>>>(S, idx, Wh, Wl);

    // 7. V[b] = W[b] @ ENTT[b]^T (= W @ ENT) -> split planes
    gemm_sp<false, false, true><<<dim3(8, 8, BATCH), 512, GSMEM_BYTES>>>(
        Wh, Wl, (long)LQ * NBE, ETh, ETl, (long)D_MODEL * NBE,
        nullptr, Vh, Vl, (long)LQ * D_MODEL, D_MODEL, NBE, nullptr, nullptr);

    // 8. P = V @ WO^T + bO -> fp32
    gemm_sp<true, false, false><<<dim3(8, 128, 1), 512, GSMEM_BYTES>>>(
        Vh, Vl, 0, WOh, WOl, 0, P, nullptr, nullptr, 0, D_MODEL, D_MODEL, WO_b, nullptr);

    // 9. LayerNorm -> out
    layernorm_k<<<ML, 256>>>(P, ln_g, ln_b, out);
}

// round 6
// speedup vs baseline: 1.8932x; 1.8395x over previous
#include <cuda_runtime.h>
#include <cuda_bf16.h>
#include <cstdint>

// ---------------------------------------------------------------------------
// Problem constants
// ---------------------------------------------------------------------------
#define D_MODEL 1024
#define BATCH   16
#define LQ      1024
#define NBE     256
#define ML (BATCH * LQ)    // 16384
#define MB (BATCH * NBE)   // 4096

// ---------------------------------------------------------------------------
// Scratch (allocation-free rule: __device__ globals)
// ---------------------------------------------------------------------------
__device__ __nv_bfloat16 g_qh  [ML * D_MODEL], g_ql  [ML * D_MODEL];  // query split
__device__ __nv_bfloat16 g_WKh [D_MODEL * D_MODEL], g_WKl [D_MODEL * D_MODEL];
__device__ __nv_bfloat16 g_WOh [D_MODEL * D_MODEL], g_WOl [D_MODEL * D_MODEL];
__device__ __nv_bfloat16 g_WQTh[D_MODEL * D_MODEL], g_WQTl[D_MODEL * D_MODEL]; // WQ^T
__device__ __nv_bfloat16 g_Gh  [MB * D_MODEL], g_Gl  [MB * D_MODEL];  // gathered ents
__device__ __nv_bfloat16 g_Eh  [MB * D_MODEL], g_El  [MB * D_MODEL];  // ENT = K-proj
__device__ __nv_bfloat16 g_EQh [MB * D_MODEL], g_EQl [MB * D_MODEL];  // ENT @ WQ
__device__ __nv_bfloat16 g_EOh [MB * D_MODEL], g_EOl [MB * D_MODEL];  // ENT @ WO^T
__device__ __nv_bfloat16 g_EOTh[MB * D_MODEL], g_EOTl[MB * D_MODEL];  // EO^T per batch
__device__ float         g_sb  [MB];                                  // bQ . ENT
__device__ float         g_S   [ML * NBE];                            // scores
__device__ __nv_bfloat16 g_Wh  [ML * NBE], g_Wl [ML * NBE];           // softmax wts
__device__ float         g_P   [ML * D_MODEL];                        // pre-LN

// ---------------------------------------------------------------------------
// Helpers
// ---------------------------------------------------------------------------
__device__ __forceinline__ void split1(float x, __nv_bfloat16& h, __nv_bfloat16& l) {
    h = __float2bfloat16(x);
    l = __float2bfloat16(x - __bfloat162float(h));
}

__device__ __forceinline__ void cp16(uint32_t dst, const void* src) {
    asm volatile("cp.async.cg.shared.global [%0], [%1], 16;"
                 :: "r"(dst), "l"(src) : "memory");
}

__device__ __forceinline__ void ldsm4(uint32_t* r, uint32_t addr) {
    asm volatile("ldmatrix.sync.aligned.m8n8.x4.shared.b16 {%0,%1,%2,%3}, [%4];"
                 : "=r"(r[0]), "=r"(r[1]), "=r"(r[2]), "=r"(r[3]) : "r"(addr));
}

__device__ __forceinline__ void mma_bf16(float* c, const uint32_t* a,
                                         uint32_t b0, uint32_t b1) {
    asm volatile(
        "mma.sync.aligned.m16n8k16.row.col.f32.bf16.bf16.f32 "
        "{%0,%1,%2,%3}, {%4,%5,%6,%7}, {%8,%9}, {%0,%1,%2,%3};"
        : "+f"(c[0]), "+f"(c[1]), "+f"(c[2]), "+f"(c[3])
        : "r"(a[0]), "r"(a[1]), "r"(a[2]), "r"(a[3]), "r"(b0), "r"(b1));
}

// ---------------------------------------------------------------------------
// Split-precision bf16 NT GEMM: C[bz][M,N] = A@B^T (+bias)(*rowmask)
// 3-term: ah*bh + ah*bl + al*bh, fp32 accumulate.
// CTA 128x128, BK=32, 16 warps (4x4, warp tile 32x32),
// 3-stage cp.async pipeline, ldmatrix fragments.
// bias is indexed bias[bz*sBias + col] (sBias=0 -> shared column bias).
// ---------------------------------------------------------------------------
#define BKC 32
#define SKB 80                        // smem row stride bytes (40 bf16)
#define PLANE_B (128 * SKB)           // 10240 B
#define STAGE_B (4 * PLANE_B)         // Ah, Al, Bh, Bl = 40960 B
#define NSTAGE 3
#define GSMEM_BYTES (NSTAGE * STAGE_B)   // 122880 B

template<bool HAS_BIAS, bool MASK, bool SPLIT_OUT>
__global__ void __launch_bounds__(512, 1) gemm_sp(
    const __nv_bfloat16* __restrict__ Ahp, const __nv_bfloat16* __restrict__ Alp, long sA,
    const __nv_bfloat16* __restrict__ Bhp, const __nv_bfloat16* __restrict__ Blp, long sB,
    float* __restrict__ Cf, __nv_bfloat16* __restrict__ Ch,
    __nv_bfloat16* __restrict__ Cl, long sC,
    int N, int K,
    const float* __restrict__ bias, long sBias,
    const int* __restrict__ rmask)
{
    extern __shared__ char smc[];
    const uint32_t smb = (uint32_t)__cvta_generic_to_shared(smc);

    const int tid  = threadIdx.x;
    const int wid  = tid >> 5;
    const int lane = tid & 31;
    const int wm   = wid >> 2;       // 0..3 (32-row slab)
    const int wn   = wid & 3;        // 0..3 (32-col slab)
    const int gq   = lane >> 2;
    const int tg   = lane & 3;

    const int mtile = blockIdx.y * 128;
    const int ntile = blockIdx.x * 128;
    const int bz    = blockIdx.z;
    Ahp += (long)bz * sA;  Alp += (long)bz * sA;
    Bhp += (long)bz * sB;  Blp += (long)bz * sB;

    const int nch = K >> 5;

    float acc[2][4][4];
#pragma unroll
    for (int i = 0; i < 2; i++)
#pragma unroll
        for (int j = 0; j < 4; j++)
#pragma unroll
            for (int q = 0; q < 4; q++) acc[i][j][q] = 0.f;

    // loader: 512 threads; per plane 128 rows x 4 segs(16B) = 512 slots.
    const int lrow = tid >> 2;
    const int lseg = tid & 3;
    const long aoff = (long)(mtile + lrow) * K + lseg * 8;
    const long boff = (long)(ntile + lrow) * K + lseg * 8;
    const uint32_t sdst = lrow * SKB + lseg * 16;

    auto load_chunk = [&](int c, int s) {
        const long kofs = (long)c * BKC;
        const uint32_t sb = smb + s * STAGE_B + sdst;
        cp16(sb,               Ahp + aoff + kofs);
        cp16(sb + PLANE_B,     Alp + aoff + kofs);
        cp16(sb + 2 * PLANE_B, Bhp + boff + kofs);
        cp16(sb + 3 * PLANE_B, Blp + boff + kofs);
    };

    load_chunk(0, 0);
    asm volatile("cp.async.commit_group;" ::: "memory");
    if (nch > 1) load_chunk(1, 1);
    asm volatile("cp.async.commit_group;" ::: "memory");

    // ldmatrix per-lane address pieces
    const int lr = (lane & 7) + ((lane >> 3) & 1) * 8;   // row 0..15 within tile
    const int lc = ((lane >> 4) & 1) * 16;               // 0/16 bytes (k half)

    int stage = 0;
    for (int c = 0; c < nch; c++) {
        asm volatile("cp.async.wait_group 1;" ::: "memory");
        __syncthreads();

        const int cn = c + 2;
        if (cn < nch) {
            int sn = stage + 2; if (sn >= NSTAGE) sn -= NSTAGE;
            load_chunk(cn, sn);
        }
        asm volatile("cp.async.commit_group;" ::: "memory");

        const uint32_t stb = smb + stage * STAGE_B;

#pragma unroll
        for (int kk = 0; kk < 2; kk++) {
            uint32_t ah[2][4], al[2][4], bh[2][4], bl[2][4];
#pragma unroll
            for (int mt = 0; mt < 2; mt++) {
                uint32_t ad = stb + (uint32_t)(wm * 32 + mt * 16 + lr) * SKB
                            + kk * 32 + lc;
                ldsm4(ah[mt], ad);
                ldsm4(al[mt], ad + PLANE_B);
            }
#pragma unroll
            for (int h = 0; h < 2; h++) {
                uint32_t bd = stb + 2 * PLANE_B
                            + (uint32_t)(wn * 32 + h * 16 + lr) * SKB
                            + kk * 32 + lc;
                ldsm4(bh[h], bd);
                ldsm4(bl[h], bd + PLANE_B);
            }
#pragma unroll
            for (int mt = 0; mt < 2; mt++)
#pragma unroll
                for (int h = 0; h < 2; h++)
#pragma unroll
                    for (int j = 0; j < 2; j++) {
                        float* cc = acc[mt][h * 2 + j];
                        mma_bf16(cc, ah[mt], bh[h][j], bh[h][j + 2]);
                        mma_bf16(cc, ah[mt], bl[h][j], bl[h][j + 2]);
                        mma_bf16(cc, al[mt], bh[h][j], bh[h][j + 2]);
                    }
        }
        __syncthreads();
        stage++; if (stage >= NSTAGE) stage = 0;
    }

    // ---- epilogue ----
#pragma unroll
    for (int mt = 0; mt < 2; mt++) {
        const int r0 = mtile + wm * 32 + mt * 16 + gq;   // rows r0, r0+8
        float rm0 = 1.f, rm1 = 1.f;
        if (MASK) {
            rm0 = (rmask[r0] < 0) ? 0.f : 1.f;
            rm1 = (rmask[r0 + 8] < 0) ? 0.f : 1.f;
        }
#pragma unroll
        for (int nt = 0; nt < 4; nt++) {
            const int col = ntile + wn * 32 + nt * 8 + tg * 2;
            float bx = 0.f, by = 0.f;
            if (HAS_BIAS) {
                float2 bb = *(const float2*)(bias + bz * sBias + col);
                bx = bb.x; by = bb.y;
            }
            float o00 = (acc[mt][nt][0] + bx) * rm0;
            float o01 = (acc[mt][nt][1] + by) * rm0;
            float o10 = (acc[mt][nt][2] + bx) * rm1;
            float o11 = (acc[mt][nt][3] + by) * rm1;
            const long i0 = (long)bz * sC + (long)r0 * N + col;
            const long i1 = i0 + (long)8 * N;
            if (SPLIT_OUT) {
                __nv_bfloat162 h2, l2;
                split1(o00, h2.x, l2.x); split1(o01, h2.y, l2.y);
                *(__nv_bfloat162*)(Ch + i0) = h2;
                *(__nv_bfloat162*)(Cl + i0) = l2;
                split1(o10, h2.x, l2.x); split1(o11, h2.y, l2.y);
                *(__nv_bfloat162*)(Ch + i1) = h2;
                *(__nv_bfloat162*)(Cl + i1) = l2;
            } else {
                *(float2*)(Cf + i0) = make_float2(o00, o01);
                *(float2*)(Cf + i1) = make_float2(o10, o11);
            }
        }
    }
}

// ---------------------------------------------------------------------------
// Elementwise fp32 -> (hi, lo) bf16 split.
// ---------------------------------------------------------------------------
__global__ void split_f32(const float* __restrict__ x,
                          __nv_bfloat16* __restrict__ h,
                          __nv_bfloat16* __restrict__ l, int n4)
{
    int i = blockIdx.x * blockDim.x + threadIdx.x;
    if (i >= n4) return;
    float4 v = ((const float4*)x)[i];
    __nv_bfloat16 hh[4], ll[4];
    split1(v.x, hh[0], ll[0]); split1(v.y, hh[1], ll[1]);
    split1(v.z, hh[2], ll[2]); split1(v.w, hh[3], ll[3]);
    ((uint2*)h)[i] = *(uint2*)hh;
    ((uint2*)l)[i] = *(uint2*)ll;
}

// ---------------------------------------------------------------------------
// Split + transpose of a (D,D) fp32 matrix: T[d,j] = W[j,d], bf16 planes.
// ---------------------------------------------------------------------------
__global__ void split_tr(const float* __restrict__ W,
                         __nv_bfloat16* __restrict__ Th,
                         __nv_bfloat16* __restrict__ Tl)
{
    __shared__ float t[32][33];
    const int c0 = blockIdx.x * 32;   // col in W (row in T)
    const int r0 = blockIdx.y * 32;   // row in W
    const int tx = threadIdx.x, ty = threadIdx.y;
#pragma unroll
    for (int i = 0; i < 32; i += 8)
        t[ty + i][tx] = W[(long)(r0 + ty + i) * D_MODEL + c0 + tx];
    __syncthreads();
#pragma unroll
    for (int i = 0; i < 32; i += 8) {
        float v = t[tx][ty + i];
        __nv_bfloat16 h, l;
        split1(v, h, l);
        const long o = (long)(c0 + ty + i) * D_MODEL + r0 + tx;
        Th[o] = h;
        Tl[o] = l;
    }
}

// ---------------------------------------------------------------------------
// Gather + split: G[r,:] = split(ent_emb[max(idx[r],0), :])
// ---------------------------------------------------------------------------
__global__ void gather_split(const float* __restrict__ E,
                             const int* __restrict__ idx,
                             __nv_bfloat16* __restrict__ Gh,
                             __nv_bfloat16* __restrict__ Gl)
{
    const int r = blockIdx.x;
    int s = idx[r];
    if (s < 0) s = 0;
    const float4* src = (const float4*)(E + (long)s * D_MODEL);
    const int i = threadIdx.x;
    float4 v = src[i];
    __nv_bfloat16 hh[4], ll[4];
    split1(v.x, hh[0], ll[0]); split1(v.y, hh[1], ll[1]);
    split1(v.z, hh[2], ll[2]); split1(v.w, hh[3], ll[3]);
    ((uint2*)(Gh + (long)r * D_MODEL))[i] = *(uint2*)hh;
    ((uint2*)(Gl + (long)r * D_MODEL))[i] = *(uint2*)ll;
}

// ---------------------------------------------------------------------------
// Score bias: sb[r] = bQ . (Eh[r] + El[r])   (fp32 accumulate)
// ---------------------------------------------------------------------------
__global__ void score_bias(const __nv_bfloat16* __restrict__ Eh,
                           const __nv_bfloat16* __restrict__ El,
                           const float* __restrict__ bQ,
                           float* __restrict__ sb)
{
    const int r = blockIdx.x;
    const int t = threadIdx.x;     // 256 threads x 4 elems
    const uint2 h2 = ((const uint2*)(Eh + (long)r * D_MODEL))[t];
    const uint2 l2 = ((const uint2*)(El + (long)r * D_MODEL))[t];
    const __nv_bfloat16* hp = (const __nv_bfloat16*)&h2;
    const __nv_bfloat16* lp = (const __nv_bfloat16*)&l2;
    float4 b = ((const float4*)bQ)[t];
    float s = (__bfloat162float(hp[0]) + __bfloat162float(lp[0])) * b.x
            + (__bfloat162float(hp[1]) + __bfloat162float(lp[1])) * b.y
            + (__bfloat162float(hp[2]) + __bfloat162float(lp[2])) * b.z
            + (__bfloat162float(hp[3]) + __bfloat162float(lp[3])) * b.w;

    __shared__ float red[8];
#pragma unroll
    for (int o = 16; o; o >>= 1) s += __shfl_xor_sync(0xffffffffu, s, o);
    if ((t & 31) == 0) red[t >> 5] = s;
    __syncthreads();
    if (t == 0) {
        float tot = 0.f;
#pragma unroll
        for (int i = 0; i < 8; i++) tot += red[i];
        sb[r] = tot;
    }
}

// ---------------------------------------------------------------------------
// Per-batch bf16 transpose of both planes: z = batch*2 + plane
// in: (NBE x D) per batch; out: (D x NBE) per batch.
// ---------------------------------------------------------------------------
__global__ void transpose_bf16(const __nv_bfloat16* __restrict__ ih,
                               const __nv_bfloat16* __restrict__ il,
                               __nv_bfloat16* __restrict__ oh,
                               __nv_bfloat16* __restrict__ ol)
{
    __shared__ __nv_bfloat16 t[32][34];
    const int b = blockIdx.z >> 1;
    const bool lo = blockIdx.z & 1;
    const __nv_bfloat16* I = (lo ? il : ih) + (long)b * NBE * D_MODEL;
    __nv_bfloat16*       O = (lo ? ol : oh) + (long)b * NBE * D_MODEL;
    const int c0 = blockIdx.x * 32;
    const int r0 = blockIdx.y * 32;
    const int tx = threadIdx.x, ty = threadIdx.y;
#pragma unroll
    for (int i = 0; i < 32; i += 8)
        t[ty + i][tx] = I[(long)(r0 + ty + i) * D_MODEL + c0 + tx];
    __syncthreads();
#pragma unroll
    for (int i = 0; i < 32; i += 8)
        O[(long)(c0 + ty + i) * NBE + r0 + tx] = t[tx][ty + i];
}

// ---------------------------------------------------------------------------
// Masked softmax over NB=256 + d^-0.5 scale, output split to bf16 planes.
// ---------------------------------------------------------------------------
__global__ void softmax_split(const float* __restrict__ S,
                              const int* __restrict__ idx,
                              __nv_bfloat16* __restrict__ Wh,
                              __nv_bfloat16* __restrict__ Wl)
{
    const int row = blockIdx.x;
    const int b   = row >> 10;
    const int n   = threadIdx.x;
    const long off = (long)row * NBE + n;

    float s = S[off];
    if (idx[b * NBE + n] < 0) s = -100000.0f;

    __shared__ float red[8];
    float m = s;
#pragma unroll
    for (int o = 16; o; o >>= 1) m = fmaxf(m, __shfl_xor_sync(0xffffffffu, m, o));
    if ((n & 31) == 0) red[n >> 5] = m;
    __syncthreads();
    float mall = red[0];
#pragma unroll
    for (int i = 1; i < 8; i++) mall = fmaxf(mall, red[i]);

    float e = expf(s - mall);
    __syncthreads();
    float t = e;
#pragma unroll
    for (int o = 16; o; o >>= 1) t += __shfl_xor_sync(0xffffffffu, t, o);
    if ((n & 31) == 0) red[n >> 5] = t;
    __syncthreads();
    float sum = 0.f;
#pragma unroll
    for (int i = 0; i < 8; i++) sum += red[i];

    float w = e * (0.03125f / sum);
    __nv_bfloat16 h, l;
    split1(w, h, l);
    Wh[off] = h;
    Wl[off] = l;
}

// ---------------------------------------------------------------------------
// Row LayerNorm over D=1024 (biased var, eps=1e-5).
// ---------------------------------------------------------------------------
__global__ void layernorm_k(const float* __restrict__ X,
                            const float* __restrict__ g,
                            const float* __restrict__ b,
                            float* __restrict__ O)
{
    const int row = blockIdx.x;
    const int t   = threadIdx.x;
    const float* x = X + (long)row * D_MODEL;

    float4 v = *(const float4*)(x + t * 4);
    float s  = v.x + v.y + v.z + v.w;
    float sq = v.x * v.x + v.y * v.y + v.z * v.z + v.w * v.w;

    __shared__ float rs[8], rq[8];
#pragma unroll
    for (int o = 16; o; o >>= 1) {
        s  += __shfl_xor_sync(0xffffffffu, s,  o);
        sq += __shfl_xor_sync(0xffffffffu, sq, o);
    }
    if ((t & 31) == 0) { rs[t >> 5] = s; rq[t >> 5] = sq; }
    __syncthreads();
    float S = 0.f, Q = 0.f;
#pragma unroll
    for (int i = 0; i < 8; i++) { S += rs[i]; Q += rq[i]; }

    float mu  = S * (1.f / 1024.f);
    float var = Q * (1.f / 1024.f) - mu * mu;
    float inv = rsqrtf(var + 1e-5f);

    float4 gg = *(const float4*)(g + t * 4);
    float4 bb = *(const float4*)(b + t * 4);
    float4 o;
    o.x = (v.x - mu) * inv * gg.x + bb.x;
    o.y = (v.y - mu) * inv * gg.y + bb.y;
    o.z = (v.z - mu) * inv * gg.z + bb.z;
    o.w = (v.w - mu) * inv * gg.w + bb.w;
    *(float4*)(O + (long)row * D_MODEL + t * 4) = o;
}

// ---------------------------------------------------------------------------
extern "C" void kernel_launch(void* const* d_in, const int* in_sizes, int n_in,
                              void* d_out, int out_size)
{
    const float* query   = (const float*)d_in[0];
    const float* ent_emb = (const float*)d_in[1];
    const int*   idx     = (const int*)  d_in[2];
    const float* WQ_w = (const float*)d_in[4];
    const float* WQ_b = (const float*)d_in[5];
    const float* WK_w = (const float*)d_in[6];
    const float* WK_b = (const float*)d_in[7];
    const float* WO_w = (const float*)d_in[8];
    const float* WO_b = (const float*)d_in[9];
    const float* ln_g = (const float*)d_in[10];
    const float* ln_b = (const float*)d_in[11];
    float* out = (float*)d_out;

    __nv_bfloat16 *qh, *ql, *WKh, *WKl, *WOh, *WOl, *WQTh, *WQTl;
    __nv_bfloat16 *Gh, *Gl, *Eh, *El, *EQh, *EQl, *EOh, *EOl, *EOTh, *EOTl, *Wh, *Wl;
    float *S, *P, *sb;
    cudaGetSymbolAddress((void**)&qh,   g_qh);   cudaGetSymbolAddress((void**)&ql,   g_ql);
    cudaGetSymbolAddress((void**)&WKh,  g_WKh);  cudaGetSymbolAddress((void**)&WKl,  g_WKl);
    cudaGetSymbolAddress((void**)&WOh,  g_WOh);  cudaGetSymbolAddress((void**)&WOl,  g_WOl);
    cudaGetSymbolAddress((void**)&WQTh, g_WQTh); cudaGetSymbolAddress((void**)&WQTl, g_WQTl);
    cudaGetSymbolAddress((void**)&Gh,   g_Gh);   cudaGetSymbolAddress((void**)&Gl,   g_Gl);
    cudaGetSymbolAddress((void**)&Eh,   g_Eh);   cudaGetSymbolAddress((void**)&El,   g_El);
    cudaGetSymbolAddress((void**)&EQh,  g_EQh);  cudaGetSymbolAddress((void**)&EQl,  g_EQl);
    cudaGetSymbolAddress((void**)&EOh,  g_EOh);  cudaGetSymbolAddress((void**)&EOl,  g_EOl);
    cudaGetSymbolAddress((void**)&EOTh, g_EOTh); cudaGetSymbolAddress((void**)&EOTl, g_EOTl);
    cudaGetSymbolAddress((void**)&Wh,   g_Wh);   cudaGetSymbolAddress((void**)&Wl,   g_Wl);
    cudaGetSymbolAddress((void**)&S,    g_S);
    cudaGetSymbolAddress((void**)&P,    g_P);
    cudaGetSymbolAddress((void**)&sb,   g_sb);

    cudaFuncSetAttribute((const void*)gemm_sp<true,  true,  true >,
        cudaFuncAttributeMaxDynamicSharedMemorySize, GSMEM_BYTES);
    cudaFuncSetAttribute((const void*)gemm_sp<false, false, true >,
        cudaFuncAttributeMaxDynamicSharedMemorySize, GSMEM_BYTES);
    cudaFuncSetAttribute((const void*)gemm_sp<true,  false, false>,
        cudaFuncAttributeMaxDynamicSharedMemorySize, GSMEM_BYTES);

    // 0. split raw inputs (query, WK, WO normal; WQ transposed for EQ GEMM)
    split_f32<<<(ML * D_MODEL / 4 + 255) / 256, 256>>>(query, qh, ql, ML * D_MODEL / 4);
    split_f32<<<(D_MODEL * D_MODEL / 4 + 255) / 256, 256>>>(WK_w, WKh, WKl, D_MODEL * D_MODEL / 4);
    split_f32<<<(D_MODEL * D_MODEL / 4 + 255) / 256, 256>>>(WO_w, WOh, WOl, D_MODEL * D_MODEL / 4);
    split_tr<<<dim3(32, 32), dim3(32, 8)>>>(WQ_w, WQTh, WQTl);

    // 1. gather + split entity rows
    gather_split<<<MB, 256>>>(ent_emb, idx, Gh, Gl);

    // 2. ENT = (G @ WK^T + bK) * mask   [4096 x 1024 x 1024]
    gemm_sp<true, true, true><<<dim3(8, 32, 1), 512, GSMEM_BYTES>>>(
        Gh, Gl, 0, WKh, WKl, 0, nullptr, Eh, El, 0,
        D_MODEL, D_MODEL, WK_b, 0, idx);

    // 3a. sb[r] = bQ . ENT[r]
    score_bias<<<MB, 256>>>(Eh, El, WQ_b, sb);

    // 3b. EQ = ENT @ WQ   (NT with B = WQ^T)   [4096 x 1024 x 1024]
    gemm_sp<false, false, true><<<dim3(8, 32, 1), 512, GSMEM_BYTES>>>(
        Eh, El, 0, WQTh, WQTl, 0, nullptr, EQh, EQl, 0,
        D_MODEL, D_MODEL, nullptr, 0, nullptr);

    // 3c. EO = ENT @ WO^T   [4096 x 1024 x 1024]
    gemm_sp<false, false, true><<<dim3(8, 32, 1), 512, GSMEM_BYTES>>>(
        Eh, El, 0, WOh, WOl, 0, nullptr, EOh, EOl, 0,
        D_MODEL, D_MODEL, nullptr, 0, nullptr);

    // 4. transpose EO per batch -> EOT (D x NBE)
    transpose_bf16<<<dim3(32, 8, BATCH * 2), dim3(32, 8)>>>(EOh, EOl, EOTh, EOTl);

    // 5. S[b] = query[b] @ EQ[b]^T + sb[b]   [16 x (1024 x 256 x 1024)]
    gemm_sp<true, false, false><<<dim3(2, 8, BATCH), 512, GSMEM_BYTES>>>(
        qh, ql, (long)LQ * D_MODEL, EQh, EQl, (long)NBE * D_MODEL,
        S, nullptr, nullptr, (long)LQ * NBE, NBE, D_MODEL, sb, NBE, nullptr);

    // 6. masked softmax + d^-0.5 scale -> split planes
    softmax_split<<<ML, NBE>>>(S, idx, Wh, Wl);

    // 7. P[b] = W[b] @ EOT[b]^T + bO  (= W @ EO + bO)  [16 x (1024 x 1024 x 256)]
    gemm_sp<true, false, false><<<dim3(8, 8, BATCH), 512, GSMEM_BYTES>>>(
        Wh, Wl, (long)LQ * NBE, EOTh, EOTl, (long)D_MODEL * NBE,
        P, nullptr, nullptr, (long)LQ * D_MODEL, D_MODEL, NBE, WO_b, 0, nullptr);

    // 8. LayerNorm -> out
    layernorm_k<<<ML, 256>>>(P, ln_g, ln_b, out);
}

// round 7
// speedup vs baseline: 1.9740x; 1.0427x over previous
#include <cuda_runtime.h>
#include <cuda_bf16.h>
#include <cstdint>

// ---------------------------------------------------------------------------
// Problem constants
// ---------------------------------------------------------------------------
#define D_MODEL 1024
#define BATCH   16
#define LQ      1024
#define NBE     256
#define ML (BATCH * LQ)    // 16384
#define MB (BATCH * NBE)   // 4096

// ---------------------------------------------------------------------------
// Scratch (allocation-free rule: __device__ globals)
// ---------------------------------------------------------------------------
__device__ __nv_bfloat16 g_qh  [ML * D_MODEL], g_ql  [ML * D_MODEL];
__device__ __nv_bfloat16 g_WKh [D_MODEL * D_MODEL], g_WKl [D_MODEL * D_MODEL];
__device__ __nv_bfloat16 g_WOh [D_MODEL * D_MODEL], g_WOl [D_MODEL * D_MODEL];
__device__ __nv_bfloat16 g_WQTh[D_MODEL * D_MODEL], g_WQTl[D_MODEL * D_MODEL];
__device__ __nv_bfloat16 g_Gh  [MB * D_MODEL], g_Gl  [MB * D_MODEL];
__device__ __nv_bfloat16 g_Eh  [MB * D_MODEL], g_El  [MB * D_MODEL];
__device__ __nv_bfloat16 g_EQh [MB * D_MODEL], g_EQl [MB * D_MODEL];
__device__ __nv_bfloat16 g_EOh [MB * D_MODEL], g_EOl [MB * D_MODEL];
__device__ __nv_bfloat16 g_EOTh[MB * D_MODEL], g_EOTl[MB * D_MODEL];
__device__ float         g_sb  [MB];
__device__ float         g_S   [ML * NBE];
__device__ __nv_bfloat16 g_Wh  [ML * NBE], g_Wl [ML * NBE];
__device__ float         g_P   [ML * D_MODEL];

// ---------------------------------------------------------------------------
// Helpers
// ---------------------------------------------------------------------------
__device__ __forceinline__ void split1(float x, __nv_bfloat16& h, __nv_bfloat16& l) {
    h = __float2bfloat16(x);
    l = __float2bfloat16(x - __bfloat162float(h));
}

__device__ __forceinline__ void cp16(uint32_t dst, const void* src) {
    asm volatile("cp.async.cg.shared.global [%0], [%1], 16;"
                 :: "r"(dst), "l"(src) : "memory");
}

__device__ __forceinline__ void ldsm4(uint32_t* r, uint32_t addr) {
    asm volatile("ldmatrix.sync.aligned.m8n8.x4.shared.b16 {%0,%1,%2,%3}, [%4];"
                 : "=r"(r[0]), "=r"(r[1]), "=r"(r[2]), "=r"(r[3]) : "r"(addr));
}

__device__ __forceinline__ void mma_bf16(float* c, const uint32_t* a,
                                         uint32_t b0, uint32_t b1) {
    asm volatile(
        "mma.sync.aligned.m16n8k16.row.col.f32.bf16.bf16.f32 "
        "{%0,%1,%2,%3}, {%4,%5,%6,%7}, {%8,%9}, {%0,%1,%2,%3};"
        : "+f"(c[0]), "+f"(c[1]), "+f"(c[2]), "+f"(c[3])
        : "r"(a[0]), "r"(a[1]), "r"(a[2]), "r"(a[3]), "r"(b0), "r"(b1));
}

// ---------------------------------------------------------------------------
// Split-precision bf16 NT GEMM: C[bz][M,N] = A@B^T (+bias)(*rowmask)
// 3-term: ah*bh + ah*bl + al*bh, fp32 accumulate.
// CTA 128x128, BK=32, 8 warps (2x4, warp tile 64x32),
// 2-stage cp.async pipeline, 256 threads, 2 CTAs/SM.
// bias indexed bias[bz*sBias + col].
// ---------------------------------------------------------------------------
#define BKC 32
#define SKB 80                        // smem row stride bytes (40 bf16)
#define PLANE_B (128 * SKB)           // 10240 B
#define STAGE_B (4 * PLANE_B)         // Ah, Al, Bh, Bl = 40960 B
#define GSMEM_BYTES (2 * STAGE_B)     // 81920 B

template<bool HAS_BIAS, bool MASK, bool SPLIT_OUT>
__global__ void __launch_bounds__(256, 2) gemm_sp(
    const __nv_bfloat16* __restrict__ Ahp, const __nv_bfloat16* __restrict__ Alp, long sA,
    const __nv_bfloat16* __restrict__ Bhp, const __nv_bfloat16* __restrict__ Blp, long sB,
    float* __restrict__ Cf, __nv_bfloat16* __restrict__ Ch,
    __nv_bfloat16* __restrict__ Cl, long sC,
    int N, int K,
    const float* __restrict__ bias, long sBias,
    const int* __restrict__ rmask)
{
    extern __shared__ char smc[];
    const uint32_t smb = (uint32_t)__cvta_generic_to_shared(smc);

    const int tid  = threadIdx.x;
    const int wid  = tid >> 5;
    const int lane = tid & 31;
    const int wm   = wid >> 2;       // 0..1 (64-row slab)
    const int wn   = wid & 3;        // 0..3 (32-col slab)
    const int gq   = lane >> 2;
    const int tg   = lane & 3;

    const int mtile = blockIdx.y * 128;
    const int ntile = blockIdx.x * 128;
    const int bz    = blockIdx.z;
    Ahp += (long)bz * sA;  Alp += (long)bz * sA;
    Bhp += (long)bz * sB;  Blp += (long)bz * sB;

    const int nch = K >> 5;

    float acc[4][4][4];
#pragma unroll
    for (int i = 0; i < 4; i++)
#pragma unroll
        for (int j = 0; j < 4; j++)
#pragma unroll
            for (int q = 0; q < 4; q++) acc[i][j][q] = 0.f;

    // loader: 256 threads, per plane 512 slots (128 rows x 4 segs of 16B)
    // thread handles slots tid and tid+256 -> rows r and r+64, same seg.
    const int lrow = tid >> 2;            // 0..63
    const int lseg = tid & 3;
    const long aoff = (long)(mtile + lrow) * K + lseg * 8;
    const long boff = (long)(ntile + lrow) * K + lseg * 8;
    const long half = (long)64 * K;
    const uint32_t sdst = lrow * SKB + lseg * 16;
    const uint32_t shalf = 64 * SKB;

    auto load_chunk = [&](int c, int s) {
        const long kofs = (long)c * BKC;
        const uint32_t sb = smb + s * STAGE_B + sdst;
        cp16(sb,                        Ahp + aoff + kofs);
        cp16(sb + shalf,                Ahp + aoff + half + kofs);
        cp16(sb + PLANE_B,              Alp + aoff + kofs);
        cp16(sb + PLANE_B + shalf,      Alp + aoff + half + kofs);
        cp16(sb + 2 * PLANE_B,          Bhp + boff + kofs);
        cp16(sb + 2 * PLANE_B + shalf,  Bhp + boff + half + kofs);
        cp16(sb + 3 * PLANE_B,          Blp + boff + kofs);
        cp16(sb + 3 * PLANE_B + shalf,  Blp + boff + half + kofs);
    };

    load_chunk(0, 0);
    asm volatile("cp.async.commit_group;" ::: "memory");

    // ldmatrix per-lane address pieces
    const int lr = (lane & 7) + ((lane >> 3) & 1) * 8;   // row 0..15 within tile
    const int lc = ((lane >> 4) & 1) * 16;               // 0/16 bytes (k half)

    for (int c = 0; c < nch; c++) {
        const int s = c & 1;
        if (c + 1 < nch) {
            load_chunk(c + 1, s ^ 1);
            asm volatile("cp.async.commit_group;" ::: "memory");
            asm volatile("cp.async.wait_group 1;" ::: "memory");
        } else {
            asm volatile("cp.async.wait_group 0;" ::: "memory");
        }
        __syncthreads();

        const uint32_t stb = smb + s * STAGE_B;

#pragma unroll
        for (int kk = 0; kk < 2; kk++) {
            uint32_t bh[2][4], bl[2][4];
#pragma unroll
            for (int h = 0; h < 2; h++) {
                uint32_t bd = stb + 2 * PLANE_B
                            + (uint32_t)(wn * 32 + h * 16 + lr) * SKB
                            + kk * 32 + lc;
                ldsm4(bh[h], bd);
                ldsm4(bl[h], bd + PLANE_B);
            }
            // process A fragments in pairs of m-tiles to bound registers
#pragma unroll
            for (int mp = 0; mp < 2; mp++) {
                uint32_t ah[2][4], al[2][4];
#pragma unroll
                for (int m2 = 0; m2 < 2; m2++) {
                    uint32_t ad = stb
                        + (uint32_t)(wm * 64 + (mp * 2 + m2) * 16 + lr) * SKB
                        + kk * 32 + lc;
                    ldsm4(ah[m2], ad);
                    ldsm4(al[m2], ad + PLANE_B);
                }
#pragma unroll
                for (int m2 = 0; m2 < 2; m2++)
#pragma unroll
                    for (int h = 0; h < 2; h++)
#pragma unroll
                        for (int j = 0; j < 2; j++) {
                            float* cc = acc[mp * 2 + m2][h * 2 + j];
                            mma_bf16(cc, ah[m2], bh[h][j], bh[h][j + 2]);
                            mma_bf16(cc, ah[m2], bl[h][j], bl[h][j + 2]);
                            mma_bf16(cc, al[m2], bh[h][j], bh[h][j + 2]);
                        }
            }
        }
        __syncthreads();
    }

    // ---- epilogue ----
#pragma unroll
    for (int mt = 0; mt < 4; mt++) {
        const int r0 = mtile + wm * 64 + mt * 16 + gq;   // rows r0, r0+8
        float rm0 = 1.f, rm1 = 1.f;
        if (MASK) {
            rm0 = (rmask[r0] < 0) ? 0.f : 1.f;
            rm1 = (rmask[r0 + 8] < 0) ? 0.f : 1.f;
        }
#pragma unroll
        for (int nt = 0; nt < 4; nt++) {
            const int col = ntile + wn * 32 + nt * 8 + tg * 2;
            float bx = 0.f, by = 0.f;
            if (HAS_BIAS) {
                float2 bb = *(const float2*)(bias + bz * sBias + col);
                bx = bb.x; by = bb.y;
            }
            float o00 = (acc[mt][nt][0] + bx) * rm0;
            float o01 = (acc[mt][nt][1] + by) * rm0;
            float o10 = (acc[mt][nt][2] + bx) * rm1;
            float o11 = (acc[mt][nt][3] + by) * rm1;
            const long i0 = (long)bz * sC + (long)r0 * N + col;
            const long i1 = i0 + (long)8 * N;
            if (SPLIT_OUT) {
                __nv_bfloat162 h2, l2;
                split1(o00, h2.x, l2.x); split1(o01, h2.y, l2.y);
                *(__nv_bfloat162*)(Ch + i0) = h2;
                *(__nv_bfloat162*)(Cl + i0) = l2;
                split1(o10, h2.x, l2.x); split1(o11, h2.y, l2.y);
                *(__nv_bfloat162*)(Ch + i1) = h2;
                *(__nv_bfloat162*)(Cl + i1) = l2;
            } else {
                *(float2*)(Cf + i0) = make_float2(o00, o01);
                *(float2*)(Cf + i1) = make_float2(o10, o11);
            }
        }
    }
}

// ---------------------------------------------------------------------------
// Elementwise fp32 -> (hi, lo) bf16 split.
// ---------------------------------------------------------------------------
__global__ void split_f32(const float* __restrict__ x,
                          __nv_bfloat16* __restrict__ h,
                          __nv_bfloat16* __restrict__ l, int n4)
{
    int i = blockIdx.x * blockDim.x + threadIdx.x;
    if (i >= n4) return;
    float4 v = ((const float4*)x)[i];
    __nv_bfloat16 hh[4], ll[4];
    split1(v.x, hh[0], ll[0]); split1(v.y, hh[1], ll[1]);
    split1(v.z, hh[2], ll[2]); split1(v.w, hh[3], ll[3]);
    ((uint2*)h)[i] = *(uint2*)hh;
    ((uint2*)l)[i] = *(uint2*)ll;
}

// ---------------------------------------------------------------------------
// Split + transpose of a (D,D) fp32 matrix: T[d,j] = W[j,d], bf16 planes.
// ---------------------------------------------------------------------------
__global__ void split_tr(const float* __restrict__ W,
                         __nv_bfloat16* __restrict__ Th,
                         __nv_bfloat16* __restrict__ Tl)
{
    __shared__ float t[32][33];
    const int c0 = blockIdx.x * 32;
    const int r0 = blockIdx.y * 32;
    const int tx = threadIdx.x, ty = threadIdx.y;
#pragma unroll
    for (int i = 0; i < 32; i += 8)
        t[ty + i][tx] = W[(long)(r0 + ty + i) * D_MODEL + c0 + tx];
    __syncthreads();
#pragma unroll
    for (int i = 0; i < 32; i += 8) {
        float v = t[tx][ty + i];
        __nv_bfloat16 h, l;
        split1(v, h, l);
        const long o = (long)(c0 + ty + i) * D_MODEL + r0 + tx;
        Th[o] = h;
        Tl[o] = l;
    }
}

// ---------------------------------------------------------------------------
// Gather + split: G[r,:] = split(ent_emb[max(idx[r],0), :])
// ---------------------------------------------------------------------------
__global__ void gather_split(const float* __restrict__ E,
                             const int* __restrict__ idx,
                             __nv_bfloat16* __restrict__ Gh,
                             __nv_bfloat16* __restrict__ Gl)
{
    const int r = blockIdx.x;
    int s = idx[r];
    if (s < 0) s = 0;
    const float4* src = (const float4*)(E + (long)s * D_MODEL);
    const int i = threadIdx.x;
    float4 v = src[i];
    __nv_bfloat16 hh[4], ll[4];
    split1(v.x, hh[0], ll[0]); split1(v.y, hh[1], ll[1]);
    split1(v.z, hh[2], ll[2]); split1(v.w, hh[3], ll[3]);
    ((uint2*)(Gh + (long)r * D_MODEL))[i] = *(uint2*)hh;
    ((uint2*)(Gl + (long)r * D_MODEL))[i] = *(uint2*)ll;
}

// ---------------------------------------------------------------------------
// Score bias: sb[r] = bQ . (Eh[r] + El[r])
// ---------------------------------------------------------------------------
__global__ void score_bias(const __nv_bfloat16* __restrict__ Eh,
                           const __nv_bfloat16* __restrict__ El,
                           const float* __restrict__ bQ,
                           float* __restrict__ sb)
{
    const int r = blockIdx.x;
    const int t = threadIdx.x;
    const uint2 h2 = ((const uint2*)(Eh + (long)r * D_MODEL))[t];
    const uint2 l2 = ((const uint2*)(El + (long)r * D_MODEL))[t];
    const __nv_bfloat16* hp = (const __nv_bfloat16*)&h2;
    const __nv_bfloat16* lp = (const __nv_bfloat16*)&l2;
    float4 b = ((const float4*)bQ)[t];
    float s = (__bfloat162float(hp[0]) + __bfloat162float(lp[0])) * b.x
            + (__bfloat162float(hp[1]) + __bfloat162float(lp[1])) * b.y
            + (__bfloat162float(hp[2]) + __bfloat162float(lp[2])) * b.z
            + (__bfloat162float(hp[3]) + __bfloat162float(lp[3])) * b.w;

    __shared__ float red[8];
#pragma unroll
    for (int o = 16; o; o >>= 1) s += __shfl_xor_sync(0xffffffffu, s, o);
    if ((t & 31) == 0) red[t >> 5] = s;
    __syncthreads();
    if (t == 0) {
        float tot = 0.f;
#pragma unroll
        for (int i = 0; i < 8; i++) tot += red[i];
        sb[r] = tot;
    }
}

// ---------------------------------------------------------------------------
// Per-batch bf16 transpose of both planes: z = batch*2 + plane
// ---------------------------------------------------------------------------
__global__ void transpose_bf16(const __nv_bfloat16* __restrict__ ih,
                               const __nv_bfloat16* __restrict__ il,
                               __nv_bfloat16* __restrict__ oh,
                               __nv_bfloat16* __restrict__ ol)
{
    __shared__ __nv_bfloat16 t[32][34];
    const int b = blockIdx.z >> 1;
    const bool lo = blockIdx.z & 1;
    const __nv_bfloat16* I = (lo ? il : ih) + (long)b * NBE * D_MODEL;
    __nv_bfloat16*       O = (lo ? ol : oh) + (long)b * NBE * D_MODEL;
    const int c0 = blockIdx.x * 32;
    const int r0 = blockIdx.y * 32;
    const int tx = threadIdx.x, ty = threadIdx.y;
#pragma unroll
    for (int i = 0; i < 32; i += 8)
        t[ty + i][tx] = I[(long)(r0 + ty + i) * D_MODEL + c0 + tx];
    __syncthreads();
#pragma unroll
    for (int i = 0; i < 32; i += 8)
        O[(long)(c0 + ty + i) * NBE + r0 + tx] = t[tx][ty + i];
}

// ---------------------------------------------------------------------------
// Masked softmax over NB=256 + d^-0.5 scale, output split to bf16 planes.
// ---------------------------------------------------------------------------
__global__ void softmax_split(const float* __restrict__ S,
                              const int* __restrict__ idx,
                              __nv_bfloat16* __restrict__ Wh,
                              __nv_bfloat16* __restrict__ Wl)
{
    const int row = blockIdx.x;
    const int b   = row >> 10;
    const int n   = threadIdx.x;
    const long off = (long)row * NBE + n;

    float s = S[off];
    if (idx[b * NBE + n] < 0) s = -100000.0f;

    __shared__ float red[8];
    float m = s;
#pragma unroll
    for (int o = 16; o; o >>= 1) m = fmaxf(m, __shfl_xor_sync(0xffffffffu, m, o));
    if ((n & 31) == 0) red[n >> 5] = m;
    __syncthreads();
    float mall = red[0];
#pragma unroll
    for (int i = 1; i < 8; i++) mall = fmaxf(mall, red[i]);

    float e = expf(s - mall);
    __syncthreads();
    float t = e;
#pragma unroll
    for (int o = 16; o; o >>= 1) t += __shfl_xor_sync(0xffffffffu, t, o);
    if ((n & 31) == 0) red[n >> 5] = t;
    __syncthreads();
    float sum = 0.f;
#pragma unroll
    for (int i = 0; i < 8; i++) sum += red[i];

    float w = e * (0.03125f / sum);
    __nv_bfloat16 h, l;
    split1(w, h, l);
    Wh[off] = h;
    Wl[off] = l;
}

// ---------------------------------------------------------------------------
// Row LayerNorm over D=1024 (biased var, eps=1e-5).
// ---------------------------------------------------------------------------
__global__ void layernorm_k(const float* __restrict__ X,
                            const float* __restrict__ g,
                            const float* __restrict__ b,
                            float* __restrict__ O)
{
    const int row = blockIdx.x;
    const int t   = threadIdx.x;
    const float* x = X + (long)row * D_MODEL;

    float4 v = *(const float4*)(x + t * 4);
    float s  = v.x + v.y + v.z + v.w;
    float sq = v.x * v.x + v.y * v.y + v.z * v.z + v.w * v.w;

    __shared__ float rs[8], rq[8];
#pragma unroll
    for (int o = 16; o; o >>= 1) {
        s  += __shfl_xor_sync(0xffffffffu, s,  o);
        sq += __shfl_xor_sync(0xffffffffu, sq, o);
    }
    if ((t & 31) == 0) { rs[t >> 5] = s; rq[t >> 5] = sq; }
    __syncthreads();
    float S = 0.f, Q = 0.f;
#pragma unroll
    for (int i = 0; i < 8; i++) { S += rs[i]; Q += rq[i]; }

    float mu  = S * (1.f / 1024.f);
    float var = Q * (1.f / 1024.f) - mu * mu;
    float inv = rsqrtf(var + 1e-5f);

    float4 gg = *(const float4*)(g + t * 4);
    float4 bb = *(const float4*)(b + t * 4);
    float4 o;
    o.x = (v.x - mu) * inv * gg.x + bb.x;
    o.y = (v.y - mu) * inv * gg.y + bb.y;
    o.z = (v.z - mu) * inv * gg.z + bb.z;
    o.w = (v.w - mu) * inv * gg.w + bb.w;
    *(float4*)(O + (long)row * D_MODEL + t * 4) = o;
}

// ---------------------------------------------------------------------------
extern "C" void kernel_launch(void* const* d_in, const int* in_sizes, int n_in,
                              void* d_out, int out_size)
{
    const float* query   = (const float*)d_in[0];
    const float* ent_emb = (const float*)d_in[1];
    const int*   idx     = (const int*)  d_in[2];
    const float* WQ_w = (const float*)d_in[4];
    const float* WQ_b = (const float*)d_in[5];
    const float* WK_w = (const float*)d_in[6];
    const float* WK_b = (const float*)d_in[7];
    const float* WO_w = (const float*)d_in[8];
    const float* WO_b = (const float*)d_in[9];
    const float* ln_g = (const float*)d_in[10];
    const float* ln_b = (const float*)d_in[11];
    float* out = (float*)d_out;

    __nv_bfloat16 *qh, *ql, *WKh, *WKl, *WOh, *WOl, *WQTh, *WQTl;
    __nv_bfloat16 *Gh, *Gl, *Eh, *El, *EQh, *EQl, *EOh, *EOl, *EOTh, *EOTl, *Wh, *Wl;
    float *S, *P, *sb;
    cudaGetSymbolAddress((void**)&qh,   g_qh);   cudaGetSymbolAddress((void**)&ql,   g_ql);
    cudaGetSymbolAddress((void**)&WKh,  g_WKh);  cudaGetSymbolAddress((void**)&WKl,  g_WKl);
    cudaGetSymbolAddress((void**)&WOh,  g_WOh);  cudaGetSymbolAddress((void**)&WOl,  g_WOl);
    cudaGetSymbolAddress((void**)&WQTh, g_WQTh); cudaGetSymbolAddress((void**)&WQTl, g_WQTl);
    cudaGetSymbolAddress((void**)&Gh,   g_Gh);   cudaGetSymbolAddress((void**)&Gl,   g_Gl);
    cudaGetSymbolAddress((void**)&Eh,   g_Eh);   cudaGetSymbolAddress((void**)&El,   g_El);
    cudaGetSymbolAddress((void**)&EQh,  g_EQh);  cudaGetSymbolAddress((void**)&EQl,  g_EQl);
    cudaGetSymbolAddress((void**)&EOh,  g_EOh);  cudaGetSymbolAddress((void**)&EOl,  g_EOl);
    cudaGetSymbolAddress((void**)&EOTh, g_EOTh); cudaGetSymbolAddress((void**)&EOTl, g_EOTl);
    cudaGetSymbolAddress((void**)&Wh,   g_Wh);   cudaGetSymbolAddress((void**)&Wl,   g_Wl);
    cudaGetSymbolAddress((void**)&S,    g_S);
    cudaGetSymbolAddress((void**)&P,    g_P);
    cudaGetSymbolAddress((void**)&sb,   g_sb);

    cudaFuncSetAttribute((const void*)gemm_sp<true,  true,  true >,
        cudaFuncAttributeMaxDynamicSharedMemorySize, GSMEM_BYTES);
    cudaFuncSetAttribute((const void*)gemm_sp<false, false, true >,
        cudaFuncAttributeMaxDynamicSharedMemorySize, GSMEM_BYTES);
    cudaFuncSetAttribute((const void*)gemm_sp<true,  false, false>,
        cudaFuncAttributeMaxDynamicSharedMemorySize, GSMEM_BYTES);

    // 0. split raw inputs
    split_f32<<<(ML * D_MODEL / 4 + 255) / 256, 256>>>(query, qh, ql, ML * D_MODEL / 4);
    split_f32<<<(D_MODEL * D_MODEL / 4 + 255) / 256, 256>>>(WK_w, WKh, WKl, D_MODEL * D_MODEL / 4);
    split_f32<<<(D_MODEL * D_MODEL / 4 + 255) / 256, 256>>>(WO_w, WOh, WOl, D_MODEL * D_MODEL / 4);
    split_tr<<<dim3(32, 32), dim3(32, 8)>>>(WQ_w, WQTh, WQTl);

    // 1. gather + split entity rows
    gather_split<<<MB, 256>>>(ent_emb, idx, Gh, Gl);

    // 2. ENT = (G @ WK^T + bK) * mask   [4096 x 1024 x 1024]
    gemm_sp<true, true, true><<<dim3(8, 32, 1), 256, GSMEM_BYTES>>>(
        Gh, Gl, 0, WKh, WKl, 0, nullptr, Eh, El, 0,
        D_MODEL, D_MODEL, WK_b, 0, idx);

    // 3a. sb[r] = bQ . ENT[r]
    score_bias<<<MB, 256>>>(Eh, El, WQ_b, sb);

    // 3b. EQ = ENT @ WQ   [4096 x 1024 x 1024]
    gemm_sp<false, false, true><<<dim3(8, 32, 1), 256, GSMEM_BYTES>>>(
        Eh, El, 0, WQTh, WQTl, 0, nullptr, EQh, EQl, 0,
        D_MODEL, D_MODEL, nullptr, 0, nullptr);

    // 3c. EO = ENT @ WO^T   [4096 x 1024 x 1024]
    gemm_sp<false, false, true><<<dim3(8, 32, 1), 256, GSMEM_BYTES>>>(
        Eh, El, 0, WOh, WOl, 0, nullptr, EOh, EOl, 0,
        D_MODEL, D_MODEL, nullptr, 0, nullptr);

    // 4. transpose EO per batch -> EOT (D x NBE)
    transpose_bf16<<<dim3(32, 8, BATCH * 2), dim3(32, 8)>>>(EOh, EOl, EOTh, EOTl);

    // 5. S[b] = query[b] @ EQ[b]^T + sb[b]
    gemm_sp<true, false, false><<<dim3(2, 8, BATCH), 256, GSMEM_BYTES>>>(
        qh, ql, (long)LQ * D_MODEL, EQh, EQl, (long)NBE * D_MODEL,
        S, nullptr, nullptr, (long)LQ * NBE, NBE, D_MODEL, sb, NBE, nullptr);

    // 6. masked softmax + d^-0.5 scale -> split planes
    softmax_split<<<ML, NBE>>>(S, idx, Wh, Wl);

    // 7. P[b] = W[b] @ EOT[b]^T + bO
    gemm_sp<true, false, false><<<dim3(8, 8, BATCH), 256, GSMEM_BYTES>>>(
        Wh, Wl, (long)LQ * NBE, EOTh, EOTl, (long)D_MODEL * NBE,
        P, nullptr, nullptr, (long)LQ * D_MODEL, D_MODEL, NBE, WO_b, 0, nullptr);

    // 8. LayerNorm -> out
    layernorm_k<<<ML, 256>>>(P, ln_g, ln_b, out);
}

// round 8
// speedup vs baseline: 2.4679x; 1.2502x over previous
#include <cuda_runtime.h>
#include <cuda_bf16.h>
#include <cuda_fp16.h>
#include <cstdint>

// ---------------------------------------------------------------------------
// Problem constants
// ---------------------------------------------------------------------------
#define D_MODEL 1024
#define BATCH   16
#define LQ      1024
#define NBE     256
#define ML (BATCH * LQ)    // 16384
#define MB (BATCH * NBE)   // 4096

// ---------------------------------------------------------------------------
// Scratch (__device__ globals; no allocation anywhere)
// ---------------------------------------------------------------------------
__device__ __half         g_qh  [ML * D_MODEL], g_ql [ML * D_MODEL]; // query fp16 planes
__device__ __nv_bfloat16  g_WQTh[D_MODEL * D_MODEL], g_WQTl[D_MODEL * D_MODEL]; // WQ^T
__device__ __nv_bfloat16  g_WKTh[D_MODEL * D_MODEL], g_WKTl[D_MODEL * D_MODEL]; // WK^T
__device__ __nv_bfloat16  g_WOh [D_MODEL * D_MODEL], g_WOl [D_MODEL * D_MODEL]; // WO
__device__ __half         g_Gh  [MB * D_MODEL], g_Gl [MB * D_MODEL]; // gathered ents
__device__ __half         g_T12 [2048 * D_MODEL];                    // [T1; T2] fp16
__device__ __half         g_EQEO[MB * 2048];                         // [EQ | EO] fp16
__device__ __half         g_EOT [MB * D_MODEL];                      // EO^T per batch
__device__ float          g_sb  [MB];                                // bQ.ENT score bias
__device__ float          g_vb  [1025];                              // v = WK^T bQ, [1024]=bQ.bK
__device__ float          g_b2  [2048];                              // [bK@WQ | bK@WO^T]
__device__ float          g_S   [ML * NBE];                          // scores fp32
__device__ __half         g_Wh  [ML * NBE], g_Wl [ML * NBE];         // softmax wts fp16
__device__ float          g_P   [ML * D_MODEL];                      // pre-LN fp32

// ---------------------------------------------------------------------------
// Helpers
// ---------------------------------------------------------------------------
__device__ __forceinline__ void split1b(float x, __nv_bfloat16& h, __nv_bfloat16& l) {
    h = __float2bfloat16(x);
    l = __float2bfloat16(x - __bfloat162float(h));
}
__device__ __forceinline__ void split1h(float x, __half& h, __half& l) {
    h = __float2half_rn(x);
    l = __float2half_rn(x - __half2float(h));
}

__device__ __forceinline__ void cp16(uint32_t dst, const void* src) {
    asm volatile("cp.async.cg.shared.global [%0], [%1], 16;"
                 :: "r"(dst), "l"(src) : "memory");
}
__device__ __forceinline__ void ldsm4(uint32_t* r, uint32_t addr) {
    asm volatile("ldmatrix.sync.aligned.m8n8.x4.shared.b16 {%0,%1,%2,%3}, [%4];"
                 : "=r"(r[0]), "=r"(r[1]), "=r"(r[2]), "=r"(r[3]) : "r"(addr));
}
__device__ __forceinline__ void mma_bf16(float* c, const uint32_t* a,
                                         uint32_t b0, uint32_t b1) {
    asm volatile(
        "mma.sync.aligned.m16n8k16.row.col.f32.bf16.bf16.f32 "
        "{%0,%1,%2,%3}, {%4,%5,%6,%7}, {%8,%9}, {%0,%1,%2,%3};"
        : "+f"(c[0]), "+f"(c[1]), "+f"(c[2]), "+f"(c[3])
        : "r"(a[0]), "r"(a[1]), "r"(a[2]), "r"(a[3]), "r"(b0), "r"(b1));
}
__device__ __forceinline__ void mma_f16(float* c, const uint32_t* a,
                                        uint32_t b0, uint32_t b1) {
    asm volatile(
        "mma.sync.aligned.m16n8k16.row.col.f32.f16.f16.f32 "
        "{%0,%1,%2,%3}, {%4,%5,%6,%7}, {%8,%9}, {%0,%1,%2,%3};"
        : "+f"(c[0]), "+f"(c[1]), "+f"(c[2]), "+f"(c[3])
        : "r"(a[0]), "r"(a[1]), "r"(a[2]), "r"(a[3]), "r"(b0), "r"(b1));
}

#define BKC 32
#define SKB 80                        // smem row stride bytes (40 halves)
#define PLANE_B (128 * SKB)           // 10240 B per plane per stage

// ---------------------------------------------------------------------------
// gemm3: bf16 3-term NT GEMM (A,B 2-plane bf16) -> fp16 single-plane output.
// Used for T1 = WQT@WKT^T-style weight products. M=N=K=1024, no bias/mask.
// CTA 128x128, BK=32, 8 warps, 2-stage, 2 CTAs/SM.
// ---------------------------------------------------------------------------
#define STAGE3_B (4 * PLANE_B)        // Ah, Al, Bh, Bl
#define GSMEM3 (2 * STAGE3_B)         // 81920

__global__ void __launch_bounds__(256, 2) gemm3(
    const __nv_bfloat16* __restrict__ Ahp, const __nv_bfloat16* __restrict__ Alp,
    const __nv_bfloat16* __restrict__ Bhp, const __nv_bfloat16* __restrict__ Blp,
    __half* __restrict__ Ch)
{
    extern __shared__ char smc[];
    const uint32_t smb = (uint32_t)__cvta_generic_to_shared(smc);
    const int K = D_MODEL, N = D_MODEL;

    const int tid  = threadIdx.x;
    const int wid  = tid >> 5;
    const int lane = tid & 31;
    const int wm   = wid >> 2;
    const int wn   = wid & 3;
    const int gq   = lane >> 2;
    const int tg   = lane & 3;

    const int mtile = blockIdx.y * 128;
    const int ntile = blockIdx.x * 128;
    const int nch = K >> 5;

    float acc[4][4][4];
#pragma unroll
    for (int i = 0; i < 4; i++)
#pragma unroll
        for (int j = 0; j < 4; j++)
#pragma unroll
            for (int q = 0; q < 4; q++) acc[i][j][q] = 0.f;

    const int lrow = tid >> 2;
    const int lseg = tid & 3;
    const long aoff = (long)(mtile + lrow) * K + lseg * 8;
    const long boff = (long)(ntile + lrow) * K + lseg * 8;
    const long half = (long)64 * K;
    const uint32_t sdst = lrow * SKB + lseg * 16;
    const uint32_t shalf = 64 * SKB;

    auto load_chunk = [&](int c, int s) {
        const long kofs = (long)c * BKC;
        const uint32_t sb = smb + s * STAGE3_B + sdst;
        cp16(sb,                        Ahp + aoff + kofs);
        cp16(sb + shalf,                Ahp + aoff + half + kofs);
        cp16(sb + PLANE_B,              Alp + aoff + kofs);
        cp16(sb + PLANE_B + shalf,      Alp + aoff + half + kofs);
        cp16(sb + 2 * PLANE_B,          Bhp + boff + kofs);
        cp16(sb + 2 * PLANE_B + shalf,  Bhp + boff + half + kofs);
        cp16(sb + 3 * PLANE_B,          Blp + boff + kofs);
        cp16(sb + 3 * PLANE_B + shalf,  Blp + boff + half + kofs);
    };

    load_chunk(0, 0);
    asm volatile("cp.async.commit_group;" ::: "memory");

    const int lr = (lane & 7) + ((lane >> 3) & 1) * 8;
    const int lc = ((lane >> 4) & 1) * 16;

    for (int c = 0; c < nch; c++) {
        const int s = c & 1;
        if (c + 1 < nch) {
            load_chunk(c + 1, s ^ 1);
            asm volatile("cp.async.commit_group;" ::: "memory");
            asm volatile("cp.async.wait_group 1;" ::: "memory");
        } else {
            asm volatile("cp.async.wait_group 0;" ::: "memory");
        }
        __syncthreads();
        const uint32_t stb = smb + s * STAGE3_B;

#pragma unroll
        for (int kk = 0; kk < 2; kk++) {
            uint32_t bh[2][4], bl[2][4];
#pragma unroll
            for (int h = 0; h < 2; h++) {
                uint32_t bd = stb + 2 * PLANE_B
                            + (uint32_t)(wn * 32 + h * 16 + lr) * SKB + kk * 32 + lc;
                ldsm4(bh[h], bd);
                ldsm4(bl[h], bd + PLANE_B);
            }
#pragma unroll
            for (int mp = 0; mp < 2; mp++) {
                uint32_t ah[2][4], al[2][4];
#pragma unroll
                for (int m2 = 0; m2 < 2; m2++) {
                    uint32_t ad = stb
                        + (uint32_t)(wm * 64 + (mp * 2 + m2) * 16 + lr) * SKB
                        + kk * 32 + lc;
                    ldsm4(ah[m2], ad);
                    ldsm4(al[m2], ad + PLANE_B);
                }
#pragma unroll
                for (int m2 = 0; m2 < 2; m2++)
#pragma unroll
                    for (int h = 0; h < 2; h++)
#pragma unroll
                        for (int j = 0; j < 2; j++) {
                            float* cc = acc[mp * 2 + m2][h * 2 + j];
                            mma_bf16(cc, ah[m2], bh[h][j], bh[h][j + 2]);
                            mma_bf16(cc, ah[m2], bl[h][j], bl[h][j + 2]);
                            mma_bf16(cc, al[m2], bh[h][j], bh[h][j + 2]);
                        }
            }
        }
        __syncthreads();
    }

#pragma unroll
    for (int mt = 0; mt < 4; mt++) {
        const int r0 = mtile + wm * 64 + mt * 16 + gq;
#pragma unroll
        for (int nt = 0; nt < 4; nt++) {
            const int col = ntile + wn * 32 + nt * 8 + tg * 2;
            __half2 p0, p1;
            p0.x = __float2half_rn(acc[mt][nt][0]);
            p0.y = __float2half_rn(acc[mt][nt][1]);
            p1.x = __float2half_rn(acc[mt][nt][2]);
            p1.y = __float2half_rn(acc[mt][nt][3]);
            *(__half2*)(Ch + (long)r0 * N + col)       = p0;
            *(__half2*)(Ch + (long)(r0 + 8) * N + col) = p1;
        }
    }
}

// ---------------------------------------------------------------------------
// gemm2: fp16 2-term NT GEMM: C[bz][M,N] = (Ah+Al) @ B^T (+bias)
// A 2-plane fp16 (lda=K), B single-plane fp16 (row stride ldb).
// Output fp16 plane (F16OUT) or fp32.  bias[bz*sBias + col].
// CTA 128x128, BK=32, 8 warps, 2-stage, 2 CTAs/SM.
// ---------------------------------------------------------------------------
#define STAGE2_B (3 * PLANE_B)        // Ah, Al, B
#define GSMEM2 (2 * STAGE2_B)         // 61440

template<bool F16OUT>
__global__ void __launch_bounds__(256, 2) gemm2(
    const __half* __restrict__ Ahp, const __half* __restrict__ Alp, long sA,
    const __half* __restrict__ Bp, long sB, int ldb,
    float* __restrict__ Cf, __half* __restrict__ Ch, long sC,
    int N, int K,
    const float* __restrict__ bias, long sBias)
{
    extern __shared__ char smc[];
    const uint32_t smb = (uint32_t)__cvta_generic_to_shared(smc);

    const int tid  = threadIdx.x;
    const int wid  = tid >> 5;
    const int lane = tid & 31;
    const int wm   = wid >> 2;
    const int wn   = wid & 3;
    const int gq   = lane >> 2;
    const int tg   = lane & 3;

    const int mtile = blockIdx.y * 128;
    const int ntile = blockIdx.x * 128;
    const int bz    = blockIdx.z;
    Ahp += (long)bz * sA;  Alp += (long)bz * sA;
    Bp  += (long)bz * sB;

    const int nch = K >> 5;

    float acc[4][4][4];
#pragma unroll
    for (int i = 0; i < 4; i++)
#pragma unroll
        for (int j = 0; j < 4; j++)
#pragma unroll
            for (int q = 0; q < 4; q++) acc[i][j][q] = 0.f;

    const int lrow = tid >> 2;
    const int lseg = tid & 3;
    const long aoff = (long)(mtile + lrow) * K + lseg * 8;
    const long boff = (long)(ntile + lrow) * ldb + lseg * 8;
    const long ahalf = (long)64 * K;
    const long bhalf = (long)64 * ldb;
    const uint32_t sdst = lrow * SKB + lseg * 16;
    const uint32_t shalf = 64 * SKB;

    auto load_chunk = [&](int c, int s) {
        const long kofs = (long)c * BKC;
        const uint32_t sb = smb + s * STAGE2_B + sdst;
        cp16(sb,                        Ahp + aoff + kofs);
        cp16(sb + shalf,                Ahp + aoff + ahalf + kofs);
        cp16(sb + PLANE_B,              Alp + aoff + kofs);
        cp16(sb + PLANE_B + shalf,      Alp + aoff + ahalf + kofs);
        cp16(sb + 2 * PLANE_B,          Bp + boff + kofs);
        cp16(sb + 2 * PLANE_B + shalf,  Bp + boff + bhalf + kofs);
    };

    load_chunk(0, 0);
    asm volatile("cp.async.commit_group;" ::: "memory");

    const int lr = (lane & 7) + ((lane >> 3) & 1) * 8;
    const int lc = ((lane >> 4) & 1) * 16;

    for (int c = 0; c < nch; c++) {
        const int s = c & 1;
        if (c + 1 < nch) {
            load_chunk(c + 1, s ^ 1);
            asm volatile("cp.async.commit_group;" ::: "memory");
            asm volatile("cp.async.wait_group 1;" ::: "memory");
        } else {
            asm volatile("cp.async.wait_group 0;" ::: "memory");
        }
        __syncthreads();
        const uint32_t stb = smb + s * STAGE2_B;

#pragma unroll
        for (int kk = 0; kk < 2; kk++) {
            uint32_t bh[2][4];
#pragma unroll
            for (int h = 0; h < 2; h++) {
                uint32_t bd = stb + 2 * PLANE_B
                            + (uint32_t)(wn * 32 + h * 16 + lr) * SKB + kk * 32 + lc;
                ldsm4(bh[h], bd);
            }
#pragma unroll
            for (int mp = 0; mp < 2; mp++) {
                uint32_t ah[2][4], al[2][4];
#pragma unroll
                for (int m2 = 0; m2 < 2; m2++) {
                    uint32_t ad = stb
                        + (uint32_t)(wm * 64 + (mp * 2 + m2) * 16 + lr) * SKB
                        + kk * 32 + lc;
                    ldsm4(ah[m2], ad);
                    ldsm4(al[m2], ad + PLANE_B);
                }
#pragma unroll
                for (int m2 = 0; m2 < 2; m2++)
#pragma unroll
                    for (int h = 0; h < 2; h++)
#pragma unroll
                        for (int j = 0; j < 2; j++) {
                            float* cc = acc[mp * 2 + m2][h * 2 + j];
                            mma_f16(cc, ah[m2], bh[h][j], bh[h][j + 2]);
                            mma_f16(cc, al[m2], bh[h][j], bh[h][j + 2]);
                        }
            }
        }
        __syncthreads();
    }

#pragma unroll
    for (int mt = 0; mt < 4; mt++) {
        const int r0 = mtile + wm * 64 + mt * 16 + gq;
#pragma unroll
        for (int nt = 0; nt < 4; nt++) {
            const int col = ntile + wn * 32 + nt * 8 + tg * 2;
            float bx = 0.f, by = 0.f;
            if (bias != nullptr) {
                float2 bb = *(const float2*)(bias + bz * sBias + col);
                bx = bb.x; by = bb.y;
            }
            float o00 = acc[mt][nt][0] + bx;
            float o01 = acc[mt][nt][1] + by;
            float o10 = acc[mt][nt][2] + bx;
            float o11 = acc[mt][nt][3] + by;
            const long i0 = (long)bz * sC + (long)r0 * N + col;
            const long i1 = i0 + (long)8 * N;
            if (F16OUT) {
                __half2 p0, p1;
                p0.x = __float2half_rn(o00); p0.y = __float2half_rn(o01);
                p1.x = __float2half_rn(o10); p1.y = __float2half_rn(o11);
                *(__half2*)(Ch + i0) = p0;
                *(__half2*)(Ch + i1) = p1;
            } else {
                *(float2*)(Cf + i0) = make_float2(o00, o01);
                *(float2*)(Cf + i1) = make_float2(o10, o11);
            }
        }
    }
}

// ---------------------------------------------------------------------------
// fp32 -> fp16 hi/lo split (query)
// ---------------------------------------------------------------------------
__global__ void split_f16(const float* __restrict__ x,
                          __half* __restrict__ h, __half* __restrict__ l, int n4)
{
    int i = blockIdx.x * blockDim.x + threadIdx.x;
    if (i >= n4) return;
    float4 v = ((const float4*)x)[i];
    __half hh[4], ll[4];
    split1h(v.x, hh[0], ll[0]); split1h(v.y, hh[1], ll[1]);
    split1h(v.z, hh[2], ll[2]); split1h(v.w, hh[3], ll[3]);
    ((uint2*)h)[i] = *(uint2*)hh;
    ((uint2*)l)[i] = *(uint2*)ll;
}

// fp32 -> bf16 hi/lo split (WO)
__global__ void split_b16(const float* __restrict__ x,
                          __nv_bfloat16* __restrict__ h,
                          __nv_bfloat16* __restrict__ l, int n4)
{
    int i = blockIdx.x * blockDim.x + threadIdx.x;
    if (i >= n4) return;
    float4 v = ((const float4*)x)[i];
    __nv_bfloat16 hh[4], ll[4];
    split1b(v.x, hh[0], ll[0]); split1b(v.y, hh[1], ll[1]);
    split1b(v.z, hh[2], ll[2]); split1b(v.w, hh[3], ll[3]);
    ((uint2*)h)[i] = *(uint2*)hh;
    ((uint2*)l)[i] = *(uint2*)ll;
}

// split + transpose (D,D) fp32 -> bf16 planes of W^T
__global__ void split_tr(const float* __restrict__ W,
                         __nv_bfloat16* __restrict__ Th,
                         __nv_bfloat16* __restrict__ Tl)
{
    __shared__ float t[32][33];
    const int c0 = blockIdx.x * 32;
    const int r0 = blockIdx.y * 32;
    const int tx = threadIdx.x, ty = threadIdx.y;
#pragma unroll
    for (int i = 0; i < 32; i += 8)
        t[ty + i][tx] = W[(long)(r0 + ty + i) * D_MODEL + c0 + tx];
    __syncthreads();
#pragma unroll
    for (int i = 0; i < 32; i += 8) {
        float v = t[tx][ty + i];
        __nv_bfloat16 h, l;
        split1b(v, h, l);
        const long o = (long)(c0 + ty + i) * D_MODEL + r0 + tx;
        Th[o] = h;  Tl[o] = l;
    }
}

// ---------------------------------------------------------------------------
// prep_vec: bias2[0:1024]=bK@WQ (rows of WQT), bias2[1024:2048]=bK@WO^T (rows
// of WO), vb[0:1024]=bQ@WK (rows of WKT), vb[1024]=bQ.bK. One block per output.
// ---------------------------------------------------------------------------
__global__ void prep_vec(const __nv_bfloat16* __restrict__ WQTh,
                         const __nv_bfloat16* __restrict__ WQTl,
                         const float* __restrict__ WO,
                         const __nv_bfloat16* __restrict__ WKTh,
                         const __nv_bfloat16* __restrict__ WKTl,
                         const float* __restrict__ bK,
                         const float* __restrict__ bQ,
                         float* __restrict__ b2, float* __restrict__ vb)
{
    const int n = blockIdx.x;
    const int t = threadIdx.x;
    float s = 0.f;

    if (n < 1024) {
        const uint2 h2 = ((const uint2*)(WQTh + (long)n * D_MODEL))[t];
        const uint2 l2 = ((const uint2*)(WQTl + (long)n * D_MODEL))[t];
        const __nv_bfloat16* hp = (const __nv_bfloat16*)&h2;
        const __nv_bfloat16* lp = (const __nv_bfloat16*)&l2;
        float4 b = ((const float4*)bK)[t];
        s = (__bfloat162float(hp[0]) + __bfloat162float(lp[0])) * b.x
          + (__bfloat162float(hp[1]) + __bfloat162float(lp[1])) * b.y
          + (__bfloat162float(hp[2]) + __bfloat162float(lp[2])) * b.z
          + (__bfloat162float(hp[3]) + __bfloat162float(lp[3])) * b.w;
    } else if (n < 2048) {
        float4 w = ((const float4*)(WO + (long)(n - 1024) * D_MODEL))[t];
        float4 b = ((const float4*)bK)[t];
        s = w.x * b.x + w.y * b.y + w.z * b.z + w.w * b.w;
    } else if (n < 3072) {
        const uint2 h2 = ((const uint2*)(WKTh + (long)(n - 2048) * D_MODEL))[t];
        const uint2 l2 = ((const uint2*)(WKTl + (long)(n - 2048) * D_MODEL))[t];
        const __nv_bfloat16* hp = (const __nv_bfloat16*)&h2;
        const __nv_bfloat16* lp = (const __nv_bfloat16*)&l2;
        float4 b = ((const float4*)bQ)[t];
        s = (__bfloat162float(hp[0]) + __bfloat162float(lp[0])) * b.x
          + (__bfloat162float(hp[1]) + __bfloat162float(lp[1])) * b.y
          + (__bfloat162float(hp[2]) + __bfloat162float(lp[2])) * b.z
          + (__bfloat162float(hp[3]) + __bfloat162float(lp[3])) * b.w;
    } else {
        float4 q = ((const float4*)bQ)[t];
        float4 b = ((const float4*)bK)[t];
        s = q.x * b.x + q.y * b.y + q.z * b.z + q.w * b.w;
    }

    __shared__ float red[8];
#pragma unroll
    for (int o = 16; o; o >>= 1) s += __shfl_xor_sync(0xffffffffu, s, o);
    if ((t & 31) == 0) red[t >> 5] = s;
    __syncthreads();
    if (t == 0) {
        float tot = 0.f;
#pragma unroll
        for (int i = 0; i < 8; i++) tot += red[i];
        if (n < 2048)      b2[n] = tot;
        else if (n < 3072) vb[n - 2048] = tot;
        else               vb[1024] = tot;
    }
}

// ---------------------------------------------------------------------------
// gather + fp16 split + score-bias: G[r]=split(E[max(idx,0)]), sb[r]=G_r.v + c0
// ---------------------------------------------------------------------------
__global__ void gather_sb(const float* __restrict__ E,
                          const int* __restrict__ idx,
                          const float* __restrict__ vb,
                          __half* __restrict__ Gh, __half* __restrict__ Gl,
                          float* __restrict__ sb)
{
    const int r = blockIdx.x;
    int s = idx[r];
    if (s < 0) s = 0;
    const int i = threadIdx.x;
    float4 v = ((const float4*)(E + (long)s * D_MODEL))[i];
    __half hh[4], ll[4];
    split1h(v.x, hh[0], ll[0]); split1h(v.y, hh[1], ll[1]);
    split1h(v.z, hh[2], ll[2]); split1h(v.w, hh[3], ll[3]);
    ((uint2*)(Gh + (long)r * D_MODEL))[i] = *(uint2*)hh;
    ((uint2*)(Gl + (long)r * D_MODEL))[i] = *(uint2*)ll;

    float4 w = ((const float4*)vb)[i];
    float d = v.x * w.x + v.y * w.y + v.z * w.z + v.w * w.w;
    __shared__ float red[8];
#pragma unroll
    for (int o = 16; o; o >>= 1) d += __shfl_xor_sync(0xffffffffu, d, o);
    if ((i & 31) == 0) red[i >> 5] = d;
    __syncthreads();
    if (i == 0) {
        float tot = vb[1024];
#pragma unroll
        for (int k = 0; k < 8; k++) tot += red[k];
        sb[r] = tot;
    }
}

// ---------------------------------------------------------------------------
// per-batch fp16 transpose of the EO half of EQEO: in rows b*NBE..(+256),
// cols 1024..2047 (ld 2048) -> EOT[b] (D x NBE, ld NBE).
// ---------------------------------------------------------------------------
__global__ void transpose_f16(const __half* __restrict__ EQEO,
                              __half* __restrict__ EOT)
{
    __shared__ __half t[32][34];
    const int b  = blockIdx.z;
    const int c0 = blockIdx.x * 32;     // D cols
    const int r0 = blockIdx.y * 32;     // NBE rows
    const int tx = threadIdx.x, ty = threadIdx.y;
#pragma unroll
    for (int i = 0; i < 32; i += 8)
        t[ty + i][tx] = EQEO[(long)(b * NBE + r0 + ty + i) * 2048 + 1024 + c0 + tx];
    __syncthreads();
#pragma unroll
    for (int i = 0; i < 32; i += 8)
        EOT[(long)b * NBE * D_MODEL + (long)(c0 + ty + i) * NBE + r0 + tx]
            = t[tx][ty + i];
}

// ---------------------------------------------------------------------------
// masked softmax over NB=256 + d^-0.5 scale -> fp16 hi/lo planes
// ---------------------------------------------------------------------------
__global__ void softmax_split(const float* __restrict__ S,
                              const int* __restrict__ idx,
                              __half* __restrict__ Wh, __half* __restrict__ Wl)
{
    const int row = blockIdx.x;
    const int b   = row >> 10;
    const int n   = threadIdx.x;
    const long off = (long)row * NBE + n;

    float s = S[off];
    if (idx[b * NBE + n] < 0) s = -100000.0f;

    __shared__ float red[8];
    float m = s;
#pragma unroll
    for (int o = 16; o; o >>= 1) m = fmaxf(m, __shfl_xor_sync(0xffffffffu, m, o));
    if ((n & 31) == 0) red[n >> 5] = m;
    __syncthreads();
    float mall = red[0];
#pragma unroll
    for (int i = 1; i < 8; i++) mall = fmaxf(mall, red[i]);

    float e = expf(s - mall);
    __syncthreads();
    float t = e;
#pragma unroll
    for (int o = 16; o; o >>= 1) t += __shfl_xor_sync(0xffffffffu, t, o);
    if ((n & 31) == 0) red[n >> 5] = t;
    __syncthreads();
    float sum = 0.f;
#pragma unroll
    for (int i = 0; i < 8; i++) sum += red[i];

    float w = e * (0.03125f / sum);
    __half h, l;
    split1h(w, h, l);
    Wh[off] = h;
    Wl[off] = l;
}

// ---------------------------------------------------------------------------
// Row LayerNorm over D=1024 (biased var, eps=1e-5).
// ---------------------------------------------------------------------------
__global__ void layernorm_k(const float* __restrict__ X,
                            const float* __restrict__ g,
                            const float* __restrict__ b,
                            float* __restrict__ O)
{
    const int row = blockIdx.x;
    const int t   = threadIdx.x;
    const float* x = X + (long)row * D_MODEL;

    float4 v = *(const float4*)(x + t * 4);
    float s  = v.x + v.y + v.z + v.w;
    float sq = v.x * v.x + v.y * v.y + v.z * v.z + v.w * v.w;

    __shared__ float rs[8], rq[8];
#pragma unroll
    for (int o = 16; o; o >>= 1) {
        s  += __shfl_xor_sync(0xffffffffu, s,  o);
        sq += __shfl_xor_sync(0xffffffffu, sq, o);
    }
    if ((t & 31) == 0) { rs[t >> 5] = s; rq[t >> 5] = sq; }
    __syncthreads();
    float S = 0.f, Q = 0.f;
#pragma unroll
    for (int i = 0; i < 8; i++) { S += rs[i]; Q += rq[i]; }

    float mu  = S * (1.f / 1024.f);
    float var = Q * (1.f / 1024.f) - mu * mu;
    float inv = rsqrtf(var + 1e-5f);

    float4 gg = *(const float4*)(g + t * 4);
    float4 bb = *(const float4*)(b + t * 4);
    float4 o;
    o.x = (v.x - mu) * inv * gg.x + bb.x;
    o.y = (v.y - mu) * inv * gg.y + bb.y;
    o.z = (v.z - mu) * inv * gg.z + bb.z;
    o.w = (v.w - mu) * inv * gg.w + bb.w;
    *(float4*)(O + (long)row * D_MODEL + t * 4) = o;
}

// ---------------------------------------------------------------------------
extern "C" void kernel_launch(void* const* d_in, const int* in_sizes, int n_in,
                              void* d_out, int out_size)
{
    const float* query   = (const float*)d_in[0];
    const float* ent_emb = (const float*)d_in[1];
    const int*   idx     = (const int*)  d_in[2];
    const float* WQ_w = (const float*)d_in[4];
    const float* WQ_b = (const float*)d_in[5];
    const float* WK_w = (const float*)d_in[6];
    const float* WK_b = (const float*)d_in[7];
    const float* WO_w = (const float*)d_in[8];
    const float* WO_b = (const float*)d_in[9];
    const float* ln_g = (const float*)d_in[10];
    const float* ln_b = (const float*)d_in[11];
    float* out = (float*)d_out;

    __half *qh, *ql, *Gh, *Gl, *T12, *EQEO, *EOT, *Wh, *Wl;
    __nv_bfloat16 *WQTh, *WQTl, *WKTh, *WKTl, *WOh, *WOl;
    float *sb, *vb, *b2, *S, *P;
    cudaGetSymbolAddress((void**)&qh,   g_qh);   cudaGetSymbolAddress((void**)&ql,   g_ql);
    cudaGetSymbolAddress((void**)&WQTh, g_WQTh); cudaGetSymbolAddress((void**)&WQTl, g_WQTl);
    cudaGetSymbolAddress((void**)&WKTh, g_WKTh); cudaGetSymbolAddress((void**)&WKTl, g_WKTl);
    cudaGetSymbolAddress((void**)&WOh,  g_WOh);  cudaGetSymbolAddress((void**)&WOl,  g_WOl);
    cudaGetSymbolAddress((void**)&Gh,   g_Gh);   cudaGetSymbolAddress((void**)&Gl,   g_Gl);
    cudaGetSymbolAddress((void**)&T12,  g_T12);
    cudaGetSymbolAddress((void**)&EQEO, g_EQEO);
    cudaGetSymbolAddress((void**)&EOT,  g_EOT);
    cudaGetSymbolAddress((void**)&Wh,   g_Wh);   cudaGetSymbolAddress((void**)&Wl,   g_Wl);
    cudaGetSymbolAddress((void**)&sb,   g_sb);
    cudaGetSymbolAddress((void**)&vb,   g_vb);
    cudaGetSymbolAddress((void**)&b2,   g_b2);
    cudaGetSymbolAddress((void**)&S,    g_S);
    cudaGetSymbolAddress((void**)&P,    g_P);

    cudaFuncSetAttribute((const void*)gemm3,
        cudaFuncAttributeMaxDynamicSharedMemorySize, GSMEM3);
    cudaFuncSetAttribute((const void*)gemm2<true>,
        cudaFuncAttributeMaxDynamicSharedMemorySize, GSMEM2);
    cudaFuncSetAttribute((const void*)gemm2<false>,
        cudaFuncAttributeMaxDynamicSharedMemorySize, GSMEM2);

    const int DD4 = D_MODEL * D_MODEL / 4;

    // 0. input preprocessing
    split_f16<<<(ML * D_MODEL / 4 + 255) / 256, 256>>>(query, qh, ql, ML * D_MODEL / 4);
    split_b16<<<(DD4 + 255) / 256, 256>>>(WO_w, WOh, WOl, DD4);
    split_tr<<<dim3(32, 32), dim3(32, 8)>>>(WQ_w, WQTh, WQTl);
    split_tr<<<dim3(32, 32), dim3(32, 8)>>>(WK_w, WKTh, WKTl);
    prep_vec<<<3073, 256>>>(WQTh, WQTl, WO_w, WKTh, WKTl, WK_b, WQ_b, b2, vb);
    gather_sb<<<MB, 256>>>(ent_emb, idx, vb, Gh, Gl, sb);

    // 1. weight products: T1 = WQ^T@WK, T2 = WO@WK  (3-term bf16, fp16 out)
    gemm3<<<dim3(8, 8, 1), 256, GSMEM3>>>(WQTh, WQTl, WKTh, WKTl, T12);
    gemm3<<<dim3(8, 8, 1), 256, GSMEM3>>>(WOh,  WOl,  WKTh, WKTl, T12 + (long)1024 * D_MODEL);

    // 2. EQEO = G @ [T1;T2]^T + bias2   [4096 x 2048 x 1024], fp16 out
    gemm2<true><<<dim3(16, 32, 1), 256, GSMEM2>>>(
        Gh, Gl, 0, T12, 0, D_MODEL, nullptr, EQEO, 0,
        2048, D_MODEL, b2, 0);

    // 3. S[b] = query[b] @ EQ[b]^T + sb[b]   (EQ = EQEO cols 0:1024, ldb 2048)
    gemm2<false><<<dim3(2, 8, BATCH), 256, GSMEM2>>>(
        qh, ql, (long)LQ * D_MODEL, EQEO, (long)NBE * 2048, 2048,
        S, nullptr, (long)LQ * NBE, NBE, D_MODEL, sb, NBE);

    // 4. masked softmax + d^-0.5 -> fp16 planes
    softmax_split<<<ML, NBE>>>(S, idx, Wh, Wl);

    // 5. EOT[b] = EO[b]^T
    transpose_f16<<<dim3(32, 8, BATCH), dim3(32, 8)>>>(EQEO, EOT);

    // 6. P[b] = W[b] @ EOT[b]^T + bO   [16 x (1024 x 1024 x 256)]
    gemm2<false><<<dim3(8, 8, BATCH), 256, GSMEM2>>>(
        Wh, Wl, (long)LQ * NBE, EOT, (long)D_MODEL * NBE, NBE,
        P, nullptr, (long)LQ * D_MODEL, D_MODEL, NBE, WO_b, 0);

    // 7. LayerNorm -> out
    layernorm_k<<<ML, 256>>>(P, ln_g, ln_b, out);
}